// round 1
// baseline (speedup 1.0000x reference)
#include <cuda_runtime.h>
#include <math.h>

#define H_DIM 256
#define MAXV 10000
#define LN_EPS 1e-5f

// Scratch: [node][1024] = [Uh | Vh | Ah | Bh], plus aggregation buffer.
__device__ float g_nodebuf[(size_t)MAXV * 1024];
__device__ float g_agg[(size_t)MAXV * H_DIM];

__device__ __forceinline__ void red_add_v4(float* addr, float a, float b, float c, float d) {
    asm volatile("red.global.add.v4.f32 [%0], {%1,%2,%3,%4};"
                 :: "l"(addr), "f"(a), "f"(b), "f"(c), "f"(d) : "memory");
}

// ---------------------------------------------------------------------------
// Kernel 0: zero the aggregation buffer (graph-replay safe)
// ---------------------------------------------------------------------------
__global__ void zero_agg_kernel(int n4) {
    int i = blockIdx.x * blockDim.x + threadIdx.x;
    if (i < n4) reinterpret_cast<float4*>(g_agg)[i] = make_float4(0.f, 0.f, 0.f, 0.f);
}

// ---------------------------------------------------------------------------
// Kernel 1: fused node GEMM  C[V x 1024] = h @ [Wu|Wv|Wa|Wb]^T + bias
// NT sgemm: A = h (row-major, K contig), B = W (row-major, K contig)
// BM=64 BN=64 BK=16, 128 threads, 8x4 micro-tile
// ---------------------------------------------------------------------------
__global__ __launch_bounds__(128) void node_gemm_kernel(
    const float* __restrict__ h,
    const float* __restrict__ Wu, const float* __restrict__ bu,
    const float* __restrict__ Wv, const float* __restrict__ bv,
    const float* __restrict__ Wa, const float* __restrict__ ba,
    const float* __restrict__ Wb, const float* __restrict__ bb,
    int V)
{
    __shared__ float sA[16][64];
    __shared__ float sB[16][64];

    const int bx = blockIdx.x;       // row tile
    const int by = blockIdx.y;       // col tile 0..15
    const int tid = threadIdx.x;

    const int sel = by >> 2;         // which weight matrix
    const float* W; const float* bias;
    if      (sel == 0) { W = Wu; bias = bu; }
    else if (sel == 1) { W = Wv; bias = bv; }
    else if (sel == 2) { W = Wa; bias = ba; }
    else               { W = Wb; bias = bb; }
    const int jbase = (by & 3) * 64;  // col offset within W
    const int row0 = bx * 64;

    const int lr = tid >> 2;          // 0..31
    const int lk = (tid & 3) * 4;     // 0,4,8,12

    const int ty = tid >> 4;          // 0..7 -> rows ty*8
    const int tx = tid & 15;          // 0..15 -> cols tx*4

    float acc[8][4];
    #pragma unroll
    for (int i = 0; i < 8; i++)
        #pragma unroll
        for (int j = 0; j < 4; j++) acc[i][j] = 0.f;

    for (int kk = 0; kk < H_DIM; kk += 16) {
        #pragma unroll
        for (int half = 0; half < 2; half++) {
            int r = lr + half * 32;
            int gr = row0 + r; if (gr >= V) gr = V - 1;   // clamp (stores guarded)
            float4 v = *reinterpret_cast<const float4*>(h + (size_t)gr * H_DIM + kk + lk);
            sA[lk + 0][r] = v.x; sA[lk + 1][r] = v.y;
            sA[lk + 2][r] = v.z; sA[lk + 3][r] = v.w;
        }
        #pragma unroll
        for (int half = 0; half < 2; half++) {
            int r = lr + half * 32;
            float4 v = *reinterpret_cast<const float4*>(W + (size_t)(jbase + r) * H_DIM + kk + lk);
            sB[lk + 0][r] = v.x; sB[lk + 1][r] = v.y;
            sB[lk + 2][r] = v.z; sB[lk + 3][r] = v.w;
        }
        __syncthreads();
        #pragma unroll
        for (int k = 0; k < 16; k++) {
            float a[8], b[4];
            #pragma unroll
            for (int i = 0; i < 8; i++) a[i] = sA[k][ty * 8 + i];
            #pragma unroll
            for (int j = 0; j < 4; j++) b[j] = sB[k][tx * 4 + j];
            #pragma unroll
            for (int i = 0; i < 8; i++)
                #pragma unroll
                for (int j = 0; j < 4; j++) acc[i][j] += a[i] * b[j];
        }
        __syncthreads();
    }

    #pragma unroll
    for (int i = 0; i < 8; i++) {
        int gr = row0 + ty * 8 + i;
        if (gr < V) {
            float* out = g_nodebuf + (size_t)gr * 1024 + by * 64 + tx * 4;
            #pragma unroll
            for (int j = 0; j < 4; j++)
                out[j] = acc[i][j] + bias[jbase + tx * 4 + j];
        }
    }
}

// ---------------------------------------------------------------------------
// Kernel 2: fused edge kernel.
// Per block: 64 edges x full 256 cols.
//   Ce = e_tile @ Wc^T  (BK=16 tiled)
//   e_new = Ah[dst] + Bh[src] + Ce + bc
//   gate = sigmoid(e_new);  red.v4 atomic:  agg[src] += gate * Vh[dst]
//   e_out = e + relu(LN(e_new) * ge + be)
// 256 threads: warp ty owns rows ty*8..ty*8+7 fully (LN = warp shuffle reduce).
// Each thread: 8 rows x 8 cols accumulators.
// ---------------------------------------------------------------------------
__global__ __launch_bounds__(256) void edge_fused_kernel(
    const float* __restrict__ e,
    const int*   __restrict__ ei,      // [2][E]
    const float* __restrict__ Wc, const float* __restrict__ bc,
    const float* __restrict__ ge, const float* __restrict__ be,
    float* __restrict__ e_out,
    int E, int V)
{
    __shared__ float sA[16][64];
    __shared__ float sB[16][256];
    __shared__ int   sSrc[64], sDst[64];
    __shared__ float sBc[256], sGe[256], sBe[256];

    const int tid = threadIdx.x;       // 256
    const int e0 = blockIdx.x * 64;

    if (tid < 64) {
        sSrc[tid] = ei[e0 + tid];
        sDst[tid] = ei[E + e0 + tid];
    }
    sBc[tid] = bc[tid]; sGe[tid] = ge[tid]; sBe[tid] = be[tid];

    const int ty = tid >> 5;           // warp id 0..7 -> rows ty*8
    const int tx = tid & 31;           // lane -> cols tx*8
    const int col0 = tx * 8;

    const int lr = tid >> 2;           // 0..63
    const int lk = (tid & 3) * 4;

    float acc[8][8];
    #pragma unroll
    for (int i = 0; i < 8; i++)
        #pragma unroll
        for (int j = 0; j < 8; j++) acc[i][j] = 0.f;

    for (int kk = 0; kk < H_DIM; kk += 16) {
        {   // A tile: e rows e0+lr (E % 64 == 0 so always in-bounds)
            float4 v = *reinterpret_cast<const float4*>(e + (size_t)(e0 + lr) * H_DIM + kk + lk);
            sA[lk + 0][lr] = v.x; sA[lk + 1][lr] = v.y;
            sA[lk + 2][lr] = v.z; sA[lk + 3][lr] = v.w;
        }
        {   // B tile: Wc row j=tid, 16 k's, stored transposed
            const float* wr = Wc + (size_t)tid * H_DIM + kk;
            #pragma unroll
            for (int q = 0; q < 4; q++) {
                float4 v = *reinterpret_cast<const float4*>(wr + q * 4);
                sB[q * 4 + 0][tid] = v.x; sB[q * 4 + 1][tid] = v.y;
                sB[q * 4 + 2][tid] = v.z; sB[q * 4 + 3][tid] = v.w;
            }
        }
        __syncthreads();
        #pragma unroll
        for (int k = 0; k < 16; k++) {
            float a[8], b[8];
            #pragma unroll
            for (int i = 0; i < 8; i++) a[i] = sA[k][ty * 8 + i];
            #pragma unroll
            for (int j = 0; j < 8; j++) b[j] = sB[k][col0 + j];
            #pragma unroll
            for (int i = 0; i < 8; i++)
                #pragma unroll
                for (int j = 0; j < 8; j++) acc[i][j] += a[i] * b[j];
        }
        __syncthreads();
    }

    // ---- fused epilogue: one row at a time, whole row lives in this warp ----
    #pragma unroll
    for (int i = 0; i < 8; i++) {
        const int r = ty * 8 + i;
        const int er = e0 + r;
        const int s = sSrc[r];
        const int d = sDst[r];
        const float* ah = g_nodebuf + (size_t)d * 1024 + 512 + col0;  // Ah[dst]
        const float* bh = g_nodebuf + (size_t)s * 1024 + 768 + col0;  // Bh[src]
        const float* vh = g_nodebuf + (size_t)d * 1024 + 256 + col0;  // Vh[dst]

        float x[8];
        float sum = 0.f, sq = 0.f;
        #pragma unroll
        for (int c = 0; c < 8; c++) {
            float xv = acc[i][c] + sBc[col0 + c] + ah[c] + bh[c];
            x[c] = xv;
            sum += xv;
            sq  += xv * xv;
        }

        // gates * Vh[dst] -> atomic scatter into agg[src]
        float gv[8];
        #pragma unroll
        for (int c = 0; c < 8; c++) {
            float gt = 1.f / (1.f + __expf(-x[c]));
            gv[c] = gt * vh[c];
        }
        float* ag = g_agg + (size_t)s * H_DIM + col0;
        red_add_v4(ag,     gv[0], gv[1], gv[2], gv[3]);
        red_add_v4(ag + 4, gv[4], gv[5], gv[6], gv[7]);

        // LayerNorm over 256 cols = warp reduce (all 32 lanes hold this row)
        #pragma unroll
        for (int off = 16; off > 0; off >>= 1) {
            sum += __shfl_xor_sync(0xFFFFFFFFu, sum, off);
            sq  += __shfl_xor_sync(0xFFFFFFFFu, sq,  off);
        }
        const float mu  = sum * (1.f / 256.f);
        const float var = sq * (1.f / 256.f) - mu * mu;
        const float rs  = rsqrtf(var + LN_EPS);

        const float* erow = e     + (size_t)er * H_DIM + col0;
        float*       orow = e_out + (size_t)er * H_DIM + col0;
        #pragma unroll
        for (int c = 0; c < 8; c++) {
            float y = (x[c] - mu) * rs * sGe[col0 + c] + sBe[col0 + c];
            y = y > 0.f ? y : 0.f;
            orow[c] = erow[c] + y;
        }
    }
}

// ---------------------------------------------------------------------------
// Kernel 3: node epilogue  h_out = h + relu(LN(Uh + agg))
// One warp per node row; 8 cols per lane.
// ---------------------------------------------------------------------------
__global__ __launch_bounds__(256) void node_epilogue_kernel(
    const float* __restrict__ h,
    const float* __restrict__ gh, const float* __restrict__ bhv,
    float* __restrict__ h_out, int V)
{
    const int warp = threadIdx.x >> 5;
    const int lane = threadIdx.x & 31;
    const int n = blockIdx.x * 8 + warp;
    if (n >= V) return;
    const int col0 = lane * 8;

    const float* u  = g_nodebuf + (size_t)n * 1024 + col0;  // Uh at offset 0
    const float* ag = g_agg     + (size_t)n * H_DIM + col0;

    float x[8];
    float sum = 0.f, sq = 0.f;
    #pragma unroll
    for (int c = 0; c < 8; c++) {
        float xv = u[c] + ag[c];
        x[c] = xv;
        sum += xv;
        sq  += xv * xv;
    }
    #pragma unroll
    for (int off = 16; off > 0; off >>= 1) {
        sum += __shfl_xor_sync(0xFFFFFFFFu, sum, off);
        sq  += __shfl_xor_sync(0xFFFFFFFFu, sq,  off);
    }
    const float mu  = sum * (1.f / 256.f);
    const float var = sq * (1.f / 256.f) - mu * mu;
    const float rs  = rsqrtf(var + LN_EPS);

    const float* hr = h     + (size_t)n * H_DIM + col0;
    float*       o  = h_out + (size_t)n * H_DIM + col0;
    #pragma unroll
    for (int c = 0; c < 8; c++) {
        float y = (x[c] - mu) * rs * gh[col0 + c] + bhv[col0 + c];
        y = y > 0.f ? y : 0.f;
        o[c] = hr[c] + y;
    }
}

// ---------------------------------------------------------------------------
extern "C" void kernel_launch(void* const* d_in, const int* in_sizes, int n_in,
                              void* d_out, int out_size)
{
    const float* h  = (const float*)d_in[0];
    const float* e  = (const float*)d_in[1];
    const int*   ei = (const int*)  d_in[2];
    const float* Wu = (const float*)d_in[3];
    const float* bu = (const float*)d_in[4];
    const float* Wv = (const float*)d_in[5];
    const float* bv = (const float*)d_in[6];
    const float* Wa = (const float*)d_in[7];
    const float* ba = (const float*)d_in[8];
    const float* Wb = (const float*)d_in[9];
    const float* bb = (const float*)d_in[10];
    const float* Wc = (const float*)d_in[11];
    const float* bc = (const float*)d_in[12];
    const float* gh = (const float*)d_in[13];
    const float* bh = (const float*)d_in[14];
    const float* ge = (const float*)d_in[15];
    const float* be = (const float*)d_in[16];

    const int V = in_sizes[0] / H_DIM;
    const int E = in_sizes[1] / H_DIM;

    float* h_out = (float*)d_out;
    float* e_out = (float*)d_out + (size_t)V * H_DIM;

    // zero agg (graph-replay safe)
    const int n4 = V * (H_DIM / 4);
    zero_agg_kernel<<<(n4 + 255) / 256, 256>>>(n4);

    dim3 g1((V + 63) / 64, 1024 / 64);
    node_gemm_kernel<<<g1, 128>>>(h, Wu, bu, Wv, bv, Wa, ba, Wb, bb, V);

    edge_fused_kernel<<<E / 64, 256>>>(e, ei, Wc, bc, ge, be, e_out, E, V);

    node_epilogue_kernel<<<(V + 7) / 8, 256>>>(h, gh, bh, h_out, V);
}

// round 2
// speedup vs baseline: 1.1796x; 1.1796x over previous
#include <cuda_runtime.h>
#include <math.h>

#define H_DIM 256
#define MAXV 10000
#define LN_EPS 1e-5f

// Scratch: [node][1024] = [Uh | Vh | Ah | Bh], plus aggregation buffer.
__device__ float g_nodebuf[(size_t)MAXV * 1024];
__device__ float g_agg[(size_t)MAXV * H_DIM];

__device__ __forceinline__ void red_add_v4(float* addr, float a, float b, float c, float d) {
    asm volatile("red.global.add.v4.f32 [%0], {%1,%2,%3,%4};"
                 :: "l"(addr), "f"(a), "f"(b), "f"(c), "f"(d) : "memory");
}

__device__ __forceinline__ float to_tf32(float x) {
    float y;
    asm("cvt.rna.tf32.f32 %0, %1;" : "=f"(y) : "f"(x));
    return y;
}

__device__ __forceinline__ void mma_tf32(float& d0, float& d1, float& d2, float& d3,
                                         float a0, float a1, float a2, float a3,
                                         float b0, float b1) {
    asm volatile(
        "mma.sync.aligned.m16n8k8.row.col.f32.tf32.tf32.f32 "
        "{%0,%1,%2,%3}, {%4,%5,%6,%7}, {%8,%9}, {%0,%1,%2,%3};\n"
        : "+f"(d0), "+f"(d1), "+f"(d2), "+f"(d3)
        : "r"(__float_as_uint(a0)), "r"(__float_as_uint(a1)),
          "r"(__float_as_uint(a2)), "r"(__float_as_uint(a3)),
          "r"(__float_as_uint(b0)), "r"(__float_as_uint(b1)));
}

// ---------------------------------------------------------------------------
// Kernel 0: zero the aggregation buffer (graph-replay safe)
// ---------------------------------------------------------------------------
__global__ void zero_agg_kernel(int n4) {
    int i = blockIdx.x * blockDim.x + threadIdx.x;
    if (i < n4) reinterpret_cast<float4*>(g_agg)[i] = make_float4(0.f, 0.f, 0.f, 0.f);
}

// ---------------------------------------------------------------------------
// Kernel 1: node GEMM (tf32 mma)  C[64 x 256] per block = h @ W^T + bias
// grid = (ceil(V/64), 4); by selects {Wu,Wv,Wa,Wb} -> g_nodebuf col-group by.
// 256 threads, 8 warps; warp w owns cols [w*32, w*32+32); 4 m-tiles x 4 n-tiles.
// ---------------------------------------------------------------------------
#define SA_STRIDE 33
#define SB_STRIDE 33

__global__ __launch_bounds__(256) void node_gemm_tc_kernel(
    const float* __restrict__ h,
    const float* __restrict__ Wu, const float* __restrict__ bu,
    const float* __restrict__ Wv, const float* __restrict__ bv,
    const float* __restrict__ Wa, const float* __restrict__ ba,
    const float* __restrict__ Wb, const float* __restrict__ bb,
    int V)
{
    __shared__ float sA[64 * SA_STRIDE];
    __shared__ float sB[256 * SB_STRIDE];

    const int by = blockIdx.y;
    const float* W; const float* bias;
    if      (by == 0) { W = Wu; bias = bu; }
    else if (by == 1) { W = Wv; bias = bv; }
    else if (by == 2) { W = Wa; bias = ba; }
    else              { W = Wb; bias = bb; }

    const int tid  = threadIdx.x;
    const int w    = tid >> 5;
    const int lane = tid & 31;
    const int g    = lane >> 2;
    const int t    = lane & 3;
    const int row0 = blockIdx.x * 64;

    const int lr  = tid >> 2;          // 0..63
    const int lk8 = (tid & 3) * 8;     // 0,8,16,24

    float acc[4][4][4];
    #pragma unroll
    for (int mt = 0; mt < 4; mt++)
        #pragma unroll
        for (int nt = 0; nt < 4; nt++)
            #pragma unroll
            for (int q = 0; q < 4; q++) acc[mt][nt][q] = 0.f;

    for (int kk = 0; kk < H_DIM; kk += 32) {
        {   // A tile: 64 rows x 32 k
            int gr = row0 + lr; if (gr >= V) gr = V - 1;
            const float* ar = h + (size_t)gr * H_DIM + kk + lk8;
            float4 v0 = *reinterpret_cast<const float4*>(ar);
            float4 v1 = *reinterpret_cast<const float4*>(ar + 4);
            float* sa = sA + lr * SA_STRIDE + lk8;
            sa[0] = to_tf32(v0.x); sa[1] = to_tf32(v0.y);
            sa[2] = to_tf32(v0.z); sa[3] = to_tf32(v0.w);
            sa[4] = to_tf32(v1.x); sa[5] = to_tf32(v1.y);
            sa[6] = to_tf32(v1.z); sa[7] = to_tf32(v1.w);
        }
        {   // B tile: 256 rows (out cols) x 32 k
            const float* wr = W + (size_t)tid * H_DIM + kk;
            float* sb = sB + tid * SB_STRIDE;
            #pragma unroll
            for (int q = 0; q < 8; q++) {
                float4 v = *reinterpret_cast<const float4*>(wr + q * 4);
                sb[q * 4 + 0] = to_tf32(v.x); sb[q * 4 + 1] = to_tf32(v.y);
                sb[q * 4 + 2] = to_tf32(v.z); sb[q * 4 + 3] = to_tf32(v.w);
            }
        }
        __syncthreads();
        #pragma unroll
        for (int ks = 0; ks < 4; ks++) {
            const int kb = ks * 8;
            float bf[4][2];
            #pragma unroll
            for (int nt = 0; nt < 4; nt++) {
                int n = w * 32 + nt * 8 + g;
                bf[nt][0] = sB[n * SB_STRIDE + kb + t];
                bf[nt][1] = sB[n * SB_STRIDE + kb + t + 4];
            }
            #pragma unroll
            for (int mt = 0; mt < 4; mt++) {
                int m = mt * 16;
                float a0 = sA[(m + g) * SA_STRIDE + kb + t];
                float a1 = sA[(m + g + 8) * SA_STRIDE + kb + t];
                float a2 = sA[(m + g) * SA_STRIDE + kb + t + 4];
                float a3 = sA[(m + g + 8) * SA_STRIDE + kb + t + 4];
                #pragma unroll
                for (int nt = 0; nt < 4; nt++)
                    mma_tf32(acc[mt][nt][0], acc[mt][nt][1], acc[mt][nt][2], acc[mt][nt][3],
                             a0, a1, a2, a3, bf[nt][0], bf[nt][1]);
            }
        }
        __syncthreads();
    }

    // store + bias
    #pragma unroll
    for (int mt = 0; mt < 4; mt++) {
        #pragma unroll
        for (int nt = 0; nt < 4; nt++) {
            int c  = w * 32 + nt * 8 + 2 * t;
            int r0 = row0 + mt * 16 + g;
            int r1 = r0 + 8;
            if (r0 < V) {
                float* o = g_nodebuf + (size_t)r0 * 1024 + by * 256 + c;
                o[0] = acc[mt][nt][0] + bias[c];
                o[1] = acc[mt][nt][1] + bias[c + 1];
            }
            if (r1 < V) {
                float* o = g_nodebuf + (size_t)r1 * 1024 + by * 256 + c;
                o[0] = acc[mt][nt][2] + bias[c];
                o[1] = acc[mt][nt][3] + bias[c + 1];
            }
        }
    }
}

// ---------------------------------------------------------------------------
// Kernel 2: fused edge kernel (tf32 mma GEMM + fused gate/scatter/LN epilogue)
// Block: 64 edges x 256 cols, K=256 in chunks of 32.
// GEMM fragments staged through smem (sE, overlapping sA/sB), then the
// warp-per-row epilogue runs unchanged.
// ---------------------------------------------------------------------------
#define SE_STRIDE 260

__global__ __launch_bounds__(256) void edge_fused_tc_kernel(
    const float* __restrict__ e,
    const int*   __restrict__ ei,      // [2][E]
    const float* __restrict__ Wc, const float* __restrict__ bc,
    const float* __restrict__ ge, const float* __restrict__ be,
    float* __restrict__ e_out,
    int E, int V)
{
    extern __shared__ float smem[];
    float* sA = smem;                   // [64][33]
    float* sB = smem + 64 * SA_STRIDE;  // [256][33]
    float* sE = smem;                   // [64][260] (reuses A/B region)

    __shared__ int   sSrc[64], sDst[64];
    __shared__ float sBc[256], sGe[256], sBe[256];

    const int tid = threadIdx.x;
    const int e0  = blockIdx.x * 64;

    if (tid < 64) {
        sSrc[tid] = ei[e0 + tid];
        sDst[tid] = ei[E + e0 + tid];
    }
    sBc[tid] = bc[tid]; sGe[tid] = ge[tid]; sBe[tid] = be[tid];

    const int w    = tid >> 5;
    const int lane = tid & 31;
    const int g    = lane >> 2;
    const int t    = lane & 3;

    const int lr  = tid >> 2;
    const int lk8 = (tid & 3) * 8;

    float acc[4][4][4];
    #pragma unroll
    for (int mt = 0; mt < 4; mt++)
        #pragma unroll
        for (int nt = 0; nt < 4; nt++)
            #pragma unroll
            for (int q = 0; q < 4; q++) acc[mt][nt][q] = 0.f;

    for (int kk = 0; kk < H_DIM; kk += 32) {
        {   // A tile: e rows (E % 64 == 0)
            const float* ar = e + (size_t)(e0 + lr) * H_DIM + kk + lk8;
            float4 v0 = *reinterpret_cast<const float4*>(ar);
            float4 v1 = *reinterpret_cast<const float4*>(ar + 4);
            float* sa = sA + lr * SA_STRIDE + lk8;
            sa[0] = to_tf32(v0.x); sa[1] = to_tf32(v0.y);
            sa[2] = to_tf32(v0.z); sa[3] = to_tf32(v0.w);
            sa[4] = to_tf32(v1.x); sa[5] = to_tf32(v1.y);
            sa[6] = to_tf32(v1.z); sa[7] = to_tf32(v1.w);
        }
        {   // B tile: Wc rows
            const float* wr = Wc + (size_t)tid * H_DIM + kk;
            float* sb = sB + tid * SB_STRIDE;
            #pragma unroll
            for (int q = 0; q < 8; q++) {
                float4 v = *reinterpret_cast<const float4*>(wr + q * 4);
                sb[q * 4 + 0] = to_tf32(v.x); sb[q * 4 + 1] = to_tf32(v.y);
                sb[q * 4 + 2] = to_tf32(v.z); sb[q * 4 + 3] = to_tf32(v.w);
            }
        }
        __syncthreads();
        #pragma unroll
        for (int ks = 0; ks < 4; ks++) {
            const int kb = ks * 8;
            float bf[4][2];
            #pragma unroll
            for (int nt = 0; nt < 4; nt++) {
                int n = w * 32 + nt * 8 + g;
                bf[nt][0] = sB[n * SB_STRIDE + kb + t];
                bf[nt][1] = sB[n * SB_STRIDE + kb + t + 4];
            }
            #pragma unroll
            for (int mt = 0; mt < 4; mt++) {
                int m = mt * 16;
                float a0 = sA[(m + g) * SA_STRIDE + kb + t];
                float a1 = sA[(m + g + 8) * SA_STRIDE + kb + t];
                float a2 = sA[(m + g) * SA_STRIDE + kb + t + 4];
                float a3 = sA[(m + g + 8) * SA_STRIDE + kb + t + 4];
                #pragma unroll
                for (int nt = 0; nt < 4; nt++)
                    mma_tf32(acc[mt][nt][0], acc[mt][nt][1], acc[mt][nt][2], acc[mt][nt][3],
                             a0, a1, a2, a3, bf[nt][0], bf[nt][1]);
            }
        }
        __syncthreads();
    }

    // Stage Ce fragments into sE (reuses sA/sB region; all GEMM smem reads done)
    #pragma unroll
    for (int mt = 0; mt < 4; mt++) {
        #pragma unroll
        for (int nt = 0; nt < 4; nt++) {
            int r = mt * 16 + g;
            int c = w * 32 + nt * 8 + 2 * t;
            sE[r * SE_STRIDE + c]       = acc[mt][nt][0];
            sE[r * SE_STRIDE + c + 1]   = acc[mt][nt][1];
            sE[(r + 8) * SE_STRIDE + c]     = acc[mt][nt][2];
            sE[(r + 8) * SE_STRIDE + c + 1] = acc[mt][nt][3];
        }
    }
    __syncthreads();

    // ---- fused epilogue: warp ty owns rows ty*8..ty*8+7 fully ----
    const int ty   = w;
    const int col0 = lane * 8;

    #pragma unroll
    for (int i = 0; i < 8; i++) {
        const int r = ty * 8 + i;
        const int er = e0 + r;
        const int s = sSrc[r];
        const int d = sDst[r];
        const float* ah = g_nodebuf + (size_t)d * 1024 + 512 + col0;  // Ah[dst]
        const float* bh = g_nodebuf + (size_t)s * 1024 + 768 + col0;  // Bh[src]
        const float* vh = g_nodebuf + (size_t)d * 1024 + 256 + col0;  // Vh[dst]

        float x[8];
        {
            const float* se = sE + r * SE_STRIDE + col0;
            float4 u0 = *reinterpret_cast<const float4*>(se);
            float4 u1 = *reinterpret_cast<const float4*>(se + 4);
            x[0] = u0.x; x[1] = u0.y; x[2] = u0.z; x[3] = u0.w;
            x[4] = u1.x; x[5] = u1.y; x[6] = u1.z; x[7] = u1.w;
        }

        float sum = 0.f, sq = 0.f;
        #pragma unroll
        for (int c = 0; c < 8; c++) {
            float xv = x[c] + sBc[col0 + c] + ah[c] + bh[c];
            x[c] = xv;
            sum += xv;
            sq  += xv * xv;
        }

        // gates * Vh[dst] -> atomic scatter into agg[src]
        float gv[8];
        #pragma unroll
        for (int c = 0; c < 8; c++) {
            float gt = 1.f / (1.f + __expf(-x[c]));
            gv[c] = gt * vh[c];
        }
        float* ag = g_agg + (size_t)s * H_DIM + col0;
        red_add_v4(ag,     gv[0], gv[1], gv[2], gv[3]);
        red_add_v4(ag + 4, gv[4], gv[5], gv[6], gv[7]);

        // LayerNorm over 256 cols = warp shuffle reduce
        #pragma unroll
        for (int off = 16; off > 0; off >>= 1) {
            sum += __shfl_xor_sync(0xFFFFFFFFu, sum, off);
            sq  += __shfl_xor_sync(0xFFFFFFFFu, sq,  off);
        }
        const float mu  = sum * (1.f / 256.f);
        const float var = sq * (1.f / 256.f) - mu * mu;
        const float rs  = rsqrtf(var + LN_EPS);

        const float* erow = e     + (size_t)er * H_DIM + col0;
        float*       orow = e_out + (size_t)er * H_DIM + col0;
        #pragma unroll
        for (int c = 0; c < 8; c++) {
            float y = (x[c] - mu) * rs * sGe[col0 + c] + sBe[col0 + c];
            y = y > 0.f ? y : 0.f;
            orow[c] = erow[c] + y;
        }
    }
}

// ---------------------------------------------------------------------------
// Kernel 3: node epilogue  h_out = h + relu(LN(Uh + agg))
// ---------------------------------------------------------------------------
__global__ __launch_bounds__(256) void node_epilogue_kernel(
    const float* __restrict__ h,
    const float* __restrict__ gh, const float* __restrict__ bhv,
    float* __restrict__ h_out, int V)
{
    const int warp = threadIdx.x >> 5;
    const int lane = threadIdx.x & 31;
    const int n = blockIdx.x * 8 + warp;
    if (n >= V) return;
    const int col0 = lane * 8;

    const float* u  = g_nodebuf + (size_t)n * 1024 + col0;  // Uh at offset 0
    const float* ag = g_agg     + (size_t)n * H_DIM + col0;

    float x[8];
    float sum = 0.f, sq = 0.f;
    #pragma unroll
    for (int c = 0; c < 8; c++) {
        float xv = u[c] + ag[c];
        x[c] = xv;
        sum += xv;
        sq  += xv * xv;
    }
    #pragma unroll
    for (int off = 16; off > 0; off >>= 1) {
        sum += __shfl_xor_sync(0xFFFFFFFFu, sum, off);
        sq  += __shfl_xor_sync(0xFFFFFFFFu, sq,  off);
    }
    const float mu  = sum * (1.f / 256.f);
    const float var = sq * (1.f / 256.f) - mu * mu;
    const float rs  = rsqrtf(var + LN_EPS);

    const float* hr = h     + (size_t)n * H_DIM + col0;
    float*       o  = h_out + (size_t)n * H_DIM + col0;
    #pragma unroll
    for (int c = 0; c < 8; c++) {
        float y = (x[c] - mu) * rs * gh[col0 + c] + bhv[col0 + c];
        y = y > 0.f ? y : 0.f;
        o[c] = hr[c] + y;
    }
}

// ---------------------------------------------------------------------------
extern "C" void kernel_launch(void* const* d_in, const int* in_sizes, int n_in,
                              void* d_out, int out_size)
{
    const float* h  = (const float*)d_in[0];
    const float* e  = (const float*)d_in[1];
    const int*   ei = (const int*)  d_in[2];
    const float* Wu = (const float*)d_in[3];
    const float* bu = (const float*)d_in[4];
    const float* Wv = (const float*)d_in[5];
    const float* bv = (const float*)d_in[6];
    const float* Wa = (const float*)d_in[7];
    const float* ba = (const float*)d_in[8];
    const float* Wb = (const float*)d_in[9];
    const float* bb = (const float*)d_in[10];
    const float* Wc = (const float*)d_in[11];
    const float* bc = (const float*)d_in[12];
    const float* gh = (const float*)d_in[13];
    const float* bh = (const float*)d_in[14];
    const float* ge = (const float*)d_in[15];
    const float* be = (const float*)d_in[16];

    const int V = in_sizes[0] / H_DIM;
    const int E = in_sizes[1] / H_DIM;

    float* h_out = (float*)d_out;
    float* e_out = (float*)d_out + (size_t)V * H_DIM;

    // zero agg (graph-replay safe)
    const int n4 = V * (H_DIM / 4);
    zero_agg_kernel<<<(n4 + 255) / 256, 256>>>(n4);

    dim3 g1((V + 63) / 64, 4);
    node_gemm_tc_kernel<<<g1, 256>>>(h, Wu, bu, Wv, bv, Wa, ba, Wb, bb, V);

    static int smem_set = 0;
    const int edge_smem = 64 * SE_STRIDE * sizeof(float);  // 66560B, covers A+B too
    if (!smem_set) {
        cudaFuncSetAttribute(edge_fused_tc_kernel,
                             cudaFuncAttributeMaxDynamicSharedMemorySize, edge_smem);
        smem_set = 1;
    }
    edge_fused_tc_kernel<<<E / 64, 256, edge_smem>>>(e, ei, Wc, bc, ge, be, e_out, E, V);

    node_epilogue_kernel<<<(V + 7) / 8, 256>>>(h, gh, bh, h_out, V);
}

// round 3
// speedup vs baseline: 1.3401x; 1.1361x over previous
#include <cuda_runtime.h>
#include <math.h>

#define H_DIM 256
#define MAXV 10000
#define LN_EPS 1e-5f

// Scratch: [node][1024] = [Uh | Vh | Ah | Bh], plus aggregation buffer.
__device__ float g_nodebuf[(size_t)MAXV * 1024];
__device__ float g_agg[(size_t)MAXV * H_DIM];

// NOTE: no "memory" clobber — ordering is enforced by data dependencies on the
// operands; a clobber here acts as a compiler barrier that kills load batching
// (MLP) across the unrolled epilogue rows.
__device__ __forceinline__ void red_add_v4(float* addr, float a, float b, float c, float d) {
    asm volatile("red.global.add.v4.f32 [%0], {%1,%2,%3,%4};"
                 :: "l"(addr), "f"(a), "f"(b), "f"(c), "f"(d));
}

__device__ __forceinline__ float to_tf32(float x) {
    float y;
    asm("cvt.rna.tf32.f32 %0, %1;" : "=f"(y) : "f"(x));
    return y;
}

__device__ __forceinline__ void mma_tf32(float& d0, float& d1, float& d2, float& d3,
                                         float a0, float a1, float a2, float a3,
                                         float b0, float b1) {
    asm volatile(
        "mma.sync.aligned.m16n8k8.row.col.f32.tf32.tf32.f32 "
        "{%0,%1,%2,%3}, {%4,%5,%6,%7}, {%8,%9}, {%0,%1,%2,%3};\n"
        : "+f"(d0), "+f"(d1), "+f"(d2), "+f"(d3)
        : "r"(__float_as_uint(a0)), "r"(__float_as_uint(a1)),
          "r"(__float_as_uint(a2)), "r"(__float_as_uint(a3)),
          "r"(__float_as_uint(b0)), "r"(__float_as_uint(b1)));
}

// ---------------------------------------------------------------------------
// Kernel 0: zero the aggregation buffer (graph-replay safe)
// ---------------------------------------------------------------------------
__global__ void zero_agg_kernel(int n4) {
    int i = blockIdx.x * blockDim.x + threadIdx.x;
    if (i < n4) reinterpret_cast<float4*>(g_agg)[i] = make_float4(0.f, 0.f, 0.f, 0.f);
}

// ---------------------------------------------------------------------------
// Kernel 1: node GEMM (tf32 mma)  C[64 x 256] per block = h @ W^T + bias
// ---------------------------------------------------------------------------
#define SA_STRIDE 33
#define SB_STRIDE 33

__global__ __launch_bounds__(256) void node_gemm_tc_kernel(
    const float* __restrict__ h,
    const float* __restrict__ Wu, const float* __restrict__ bu,
    const float* __restrict__ Wv, const float* __restrict__ bv,
    const float* __restrict__ Wa, const float* __restrict__ ba,
    const float* __restrict__ Wb, const float* __restrict__ bb,
    int V)
{
    __shared__ float sA[64 * SA_STRIDE];
    __shared__ float sB[256 * SB_STRIDE];

    const int by = blockIdx.y;
    const float* W; const float* bias;
    if      (by == 0) { W = Wu; bias = bu; }
    else if (by == 1) { W = Wv; bias = bv; }
    else if (by == 2) { W = Wa; bias = ba; }
    else              { W = Wb; bias = bb; }

    const int tid  = threadIdx.x;
    const int w    = tid >> 5;
    const int lane = tid & 31;
    const int g    = lane >> 2;
    const int t    = lane & 3;
    const int row0 = blockIdx.x * 64;

    const int lr  = tid >> 2;          // 0..63
    const int lk8 = (tid & 3) * 8;     // 0,8,16,24

    float acc[4][4][4];
    #pragma unroll
    for (int mt = 0; mt < 4; mt++)
        #pragma unroll
        for (int nt = 0; nt < 4; nt++)
            #pragma unroll
            for (int q = 0; q < 4; q++) acc[mt][nt][q] = 0.f;

    for (int kk = 0; kk < H_DIM; kk += 32) {
        {   // A tile: 64 rows x 32 k (h stays L2-resident; normal policy)
            int gr = row0 + lr; if (gr >= V) gr = V - 1;
            const float* ar = h + (size_t)gr * H_DIM + kk + lk8;
            float4 v0 = __ldg(reinterpret_cast<const float4*>(ar));
            float4 v1 = __ldg(reinterpret_cast<const float4*>(ar + 4));
            float* sa = sA + lr * SA_STRIDE + lk8;
            sa[0] = to_tf32(v0.x); sa[1] = to_tf32(v0.y);
            sa[2] = to_tf32(v0.z); sa[3] = to_tf32(v0.w);
            sa[4] = to_tf32(v1.x); sa[5] = to_tf32(v1.y);
            sa[6] = to_tf32(v1.z); sa[7] = to_tf32(v1.w);
        }
        {   // B tile
            const float* wr = W + (size_t)tid * H_DIM + kk;
            float* sb = sB + tid * SB_STRIDE;
            #pragma unroll
            for (int q = 0; q < 8; q++) {
                float4 v = __ldg(reinterpret_cast<const float4*>(wr + q * 4));
                sb[q * 4 + 0] = to_tf32(v.x); sb[q * 4 + 1] = to_tf32(v.y);
                sb[q * 4 + 2] = to_tf32(v.z); sb[q * 4 + 3] = to_tf32(v.w);
            }
        }
        __syncthreads();
        #pragma unroll
        for (int ks = 0; ks < 4; ks++) {
            const int kb = ks * 8;
            float bf[4][2];
            #pragma unroll
            for (int nt = 0; nt < 4; nt++) {
                int n = w * 32 + nt * 8 + g;
                bf[nt][0] = sB[n * SB_STRIDE + kb + t];
                bf[nt][1] = sB[n * SB_STRIDE + kb + t + 4];
            }
            #pragma unroll
            for (int mt = 0; mt < 4; mt++) {
                int m = mt * 16;
                float a0 = sA[(m + g) * SA_STRIDE + kb + t];
                float a1 = sA[(m + g + 8) * SA_STRIDE + kb + t];
                float a2 = sA[(m + g) * SA_STRIDE + kb + t + 4];
                float a3 = sA[(m + g + 8) * SA_STRIDE + kb + t + 4];
                #pragma unroll
                for (int nt = 0; nt < 4; nt++)
                    mma_tf32(acc[mt][nt][0], acc[mt][nt][1], acc[mt][nt][2], acc[mt][nt][3],
                             a0, a1, a2, a3, bf[nt][0], bf[nt][1]);
            }
        }
        __syncthreads();
    }

    #pragma unroll
    for (int mt = 0; mt < 4; mt++) {
        #pragma unroll
        for (int nt = 0; nt < 4; nt++) {
            int c  = w * 32 + nt * 8 + 2 * t;
            int r0 = row0 + mt * 16 + g;
            int r1 = r0 + 8;
            if (r0 < V) {
                float* o = g_nodebuf + (size_t)r0 * 1024 + by * 256 + c;
                o[0] = acc[mt][nt][0] + bias[c];
                o[1] = acc[mt][nt][1] + bias[c + 1];
            }
            if (r1 < V) {
                float* o = g_nodebuf + (size_t)r1 * 1024 + by * 256 + c;
                o[0] = acc[mt][nt][2] + bias[c];
                o[1] = acc[mt][nt][3] + bias[c + 1];
            }
        }
    }
}

// ---------------------------------------------------------------------------
// Kernel 2: fused edge kernel (tf32 GEMM + gate/scatter/LN epilogue)
// Streaming data (e, e_out) uses .cs to keep g_nodebuf L2-resident for gathers.
// ---------------------------------------------------------------------------
#define SE_STRIDE 260

__global__ __launch_bounds__(256) void edge_fused_tc_kernel(
    const float* __restrict__ e,
    const int*   __restrict__ ei,      // [2][E]
    const float* __restrict__ Wc, const float* __restrict__ bc,
    const float* __restrict__ ge, const float* __restrict__ be,
    float* __restrict__ e_out,
    int E, int V)
{
    extern __shared__ float smem[];
    float* sA = smem;                   // [64][33]
    float* sB = smem + 64 * SA_STRIDE;  // [256][33]
    float* sE = smem;                   // [64][260] (reuses A/B region)

    __shared__ int   sSrc[64], sDst[64];
    __shared__ float sBc[256], sGe[256], sBe[256];

    const int tid = threadIdx.x;
    const int e0  = blockIdx.x * 64;

    if (tid < 64) {
        sSrc[tid] = ei[e0 + tid];
        sDst[tid] = ei[E + e0 + tid];
    }
    sBc[tid] = bc[tid]; sGe[tid] = ge[tid]; sBe[tid] = be[tid];

    const int w    = tid >> 5;
    const int lane = tid & 31;
    const int g    = lane >> 2;
    const int t    = lane & 3;

    const int lr  = tid >> 2;
    const int lk8 = (tid & 3) * 8;

    float acc[4][4][4];
    #pragma unroll
    for (int mt = 0; mt < 4; mt++)
        #pragma unroll
        for (int nt = 0; nt < 4; nt++)
            #pragma unroll
            for (int q = 0; q < 4; q++) acc[mt][nt][q] = 0.f;

    for (int kk = 0; kk < H_DIM; kk += 32) {
        {   // A tile: e rows, streaming (read once) -> evict-first
            const float* ar = e + (size_t)(e0 + lr) * H_DIM + kk + lk8;
            float4 v0 = __ldcs(reinterpret_cast<const float4*>(ar));
            float4 v1 = __ldcs(reinterpret_cast<const float4*>(ar + 4));
            float* sa = sA + lr * SA_STRIDE + lk8;
            sa[0] = to_tf32(v0.x); sa[1] = to_tf32(v0.y);
            sa[2] = to_tf32(v0.z); sa[3] = to_tf32(v0.w);
            sa[4] = to_tf32(v1.x); sa[5] = to_tf32(v1.y);
            sa[6] = to_tf32(v1.z); sa[7] = to_tf32(v1.w);
        }
        {   // B tile: Wc rows (hot, normal policy)
            const float* wr = Wc + (size_t)tid * H_DIM + kk;
            float* sb = sB + tid * SB_STRIDE;
            #pragma unroll
            for (int q = 0; q < 8; q++) {
                float4 v = __ldg(reinterpret_cast<const float4*>(wr + q * 4));
                sb[q * 4 + 0] = to_tf32(v.x); sb[q * 4 + 1] = to_tf32(v.y);
                sb[q * 4 + 2] = to_tf32(v.z); sb[q * 4 + 3] = to_tf32(v.w);
            }
        }
        __syncthreads();
        #pragma unroll
        for (int ks = 0; ks < 4; ks++) {
            const int kb = ks * 8;
            float bf[4][2];
            #pragma unroll
            for (int nt = 0; nt < 4; nt++) {
                int n = w * 32 + nt * 8 + g;
                bf[nt][0] = sB[n * SB_STRIDE + kb + t];
                bf[nt][1] = sB[n * SB_STRIDE + kb + t + 4];
            }
            #pragma unroll
            for (int mt = 0; mt < 4; mt++) {
                int m = mt * 16;
                float a0 = sA[(m + g) * SA_STRIDE + kb + t];
                float a1 = sA[(m + g + 8) * SA_STRIDE + kb + t];
                float a2 = sA[(m + g) * SA_STRIDE + kb + t + 4];
                float a3 = sA[(m + g + 8) * SA_STRIDE + kb + t + 4];
                #pragma unroll
                for (int nt = 0; nt < 4; nt++)
                    mma_tf32(acc[mt][nt][0], acc[mt][nt][1], acc[mt][nt][2], acc[mt][nt][3],
                             a0, a1, a2, a3, bf[nt][0], bf[nt][1]);
            }
        }
        __syncthreads();
    }

    // Stage Ce fragments into sE (reuses sA/sB region)
    #pragma unroll
    for (int mt = 0; mt < 4; mt++) {
        #pragma unroll
        for (int nt = 0; nt < 4; nt++) {
            int r = mt * 16 + g;
            int c = w * 32 + nt * 8 + 2 * t;
            sE[r * SE_STRIDE + c]       = acc[mt][nt][0];
            sE[r * SE_STRIDE + c + 1]   = acc[mt][nt][1];
            sE[(r + 8) * SE_STRIDE + c]     = acc[mt][nt][2];
            sE[(r + 8) * SE_STRIDE + c + 1] = acc[mt][nt][3];
        }
    }
    __syncthreads();

    // ---- fused epilogue: warp w owns rows w*8..w*8+7 fully ----
    const int col0 = lane * 8;

    #pragma unroll
    for (int i = 0; i < 8; i++) {
        const int r = w * 8 + i;
        const int er = e0 + r;
        const int s = sSrc[r];
        const int d = sDst[r];
        // L2-resident gathers (nodebuf kept hot by .cs on streaming data)
        const float4* ah = reinterpret_cast<const float4*>(g_nodebuf + (size_t)d * 1024 + 512 + col0);
        const float4* bh = reinterpret_cast<const float4*>(g_nodebuf + (size_t)s * 1024 + 768 + col0);
        const float4* vh = reinterpret_cast<const float4*>(g_nodebuf + (size_t)d * 1024 + 256 + col0);

        float4 a0 = __ldg(ah), a1 = __ldg(ah + 1);
        float4 b0 = __ldg(bh), b1 = __ldg(bh + 1);
        float4 v0 = __ldg(vh), v1 = __ldg(vh + 1);
        float4 er0 = __ldcs(reinterpret_cast<const float4*>(e + (size_t)er * H_DIM + col0));
        float4 er1 = __ldcs(reinterpret_cast<const float4*>(e + (size_t)er * H_DIM + col0 + 4));

        float x[8], vhv[8], erv[8];
        {
            const float* se = sE + r * SE_STRIDE + col0;
            float4 u0 = *reinterpret_cast<const float4*>(se);
            float4 u1 = *reinterpret_cast<const float4*>(se + 4);
            x[0] = u0.x + a0.x + b0.x; x[1] = u0.y + a0.y + b0.y;
            x[2] = u0.z + a0.z + b0.z; x[3] = u0.w + a0.w + b0.w;
            x[4] = u1.x + a1.x + b1.x; x[5] = u1.y + a1.y + b1.y;
            x[6] = u1.z + a1.z + b1.z; x[7] = u1.w + a1.w + b1.w;
        }
        vhv[0] = v0.x; vhv[1] = v0.y; vhv[2] = v0.z; vhv[3] = v0.w;
        vhv[4] = v1.x; vhv[5] = v1.y; vhv[6] = v1.z; vhv[7] = v1.w;
        erv[0] = er0.x; erv[1] = er0.y; erv[2] = er0.z; erv[3] = er0.w;
        erv[4] = er1.x; erv[5] = er1.y; erv[6] = er1.z; erv[7] = er1.w;

        float sum = 0.f, sq = 0.f;
        #pragma unroll
        for (int c = 0; c < 8; c++) {
            float xv = x[c] + sBc[col0 + c];
            x[c] = xv;
            sum += xv;
            sq  += xv * xv;
        }

        // gates * Vh[dst] -> atomic scatter into agg[src]
        float gv[8];
        #pragma unroll
        for (int c = 0; c < 8; c++) {
            float gt = 1.f / (1.f + __expf(-x[c]));
            gv[c] = gt * vhv[c];
        }
        float* ag = g_agg + (size_t)s * H_DIM + col0;
        red_add_v4(ag,     gv[0], gv[1], gv[2], gv[3]);
        red_add_v4(ag + 4, gv[4], gv[5], gv[6], gv[7]);

        // LayerNorm over 256 cols = warp shuffle reduce
        #pragma unroll
        for (int off = 16; off > 0; off >>= 1) {
            sum += __shfl_xor_sync(0xFFFFFFFFu, sum, off);
            sq  += __shfl_xor_sync(0xFFFFFFFFu, sq,  off);
        }
        const float mu  = sum * (1.f / 256.f);
        const float var = sq * (1.f / 256.f) - mu * mu;
        const float rs  = rsqrtf(var + LN_EPS);

        float4 o0, o1;
        float* ov0 = &o0.x; float* ov1 = &o1.x;
        #pragma unroll
        for (int c = 0; c < 4; c++) {
            float y = (x[c] - mu) * rs * sGe[col0 + c] + sBe[col0 + c];
            y = y > 0.f ? y : 0.f;
            ov0[c] = erv[c] + y;
        }
        #pragma unroll
        for (int c = 0; c < 4; c++) {
            float y = (x[c + 4] - mu) * rs * sGe[col0 + c + 4] + sBe[col0 + c + 4];
            y = y > 0.f ? y : 0.f;
            ov1[c] = erv[c + 4] + y;
        }
        float4* orow = reinterpret_cast<float4*>(e_out + (size_t)er * H_DIM + col0);
        __stcs(orow, o0);
        __stcs(orow + 1, o1);
    }
}

// ---------------------------------------------------------------------------
// Kernel 3: node epilogue  h_out = h + relu(LN(Uh + agg))
// ---------------------------------------------------------------------------
__global__ __launch_bounds__(256) void node_epilogue_kernel(
    const float* __restrict__ h,
    const float* __restrict__ gh, const float* __restrict__ bhv,
    float* __restrict__ h_out, int V)
{
    const int warp = threadIdx.x >> 5;
    const int lane = threadIdx.x & 31;
    const int n = blockIdx.x * 8 + warp;
    if (n >= V) return;
    const int col0 = lane * 8;

    const float4* u  = reinterpret_cast<const float4*>(g_nodebuf + (size_t)n * 1024 + col0);
    const float4* ag = reinterpret_cast<const float4*>(g_agg     + (size_t)n * H_DIM + col0);
    const float4* hr = reinterpret_cast<const float4*>(h         + (size_t)n * H_DIM + col0);

    float4 u0 = __ldcs(u),  u1 = __ldcs(u + 1);
    float4 g0 = __ldcs(ag), g1 = __ldcs(ag + 1);
    float4 h0 = __ldcs(hr), h1 = __ldcs(hr + 1);

    float x[8], hv[8];
    x[0] = u0.x + g0.x; x[1] = u0.y + g0.y; x[2] = u0.z + g0.z; x[3] = u0.w + g0.w;
    x[4] = u1.x + g1.x; x[5] = u1.y + g1.y; x[6] = u1.z + g1.z; x[7] = u1.w + g1.w;
    hv[0] = h0.x; hv[1] = h0.y; hv[2] = h0.z; hv[3] = h0.w;
    hv[4] = h1.x; hv[5] = h1.y; hv[6] = h1.z; hv[7] = h1.w;

    float sum = 0.f, sq = 0.f;
    #pragma unroll
    for (int c = 0; c < 8; c++) { sum += x[c]; sq += x[c] * x[c]; }
    #pragma unroll
    for (int off = 16; off > 0; off >>= 1) {
        sum += __shfl_xor_sync(0xFFFFFFFFu, sum, off);
        sq  += __shfl_xor_sync(0xFFFFFFFFu, sq,  off);
    }
    const float mu  = sum * (1.f / 256.f);
    const float var = sq * (1.f / 256.f) - mu * mu;
    const float rs  = rsqrtf(var + LN_EPS);

    float4 o0, o1;
    float* ov0 = &o0.x; float* ov1 = &o1.x;
    #pragma unroll
    for (int c = 0; c < 4; c++) {
        float y = (x[c] - mu) * rs * gh[col0 + c] + bhv[col0 + c];
        y = y > 0.f ? y : 0.f;
        ov0[c] = hv[c] + y;
    }
    #pragma unroll
    for (int c = 0; c < 4; c++) {
        float y = (x[c + 4] - mu) * rs * gh[col0 + c + 4] + bhv[col0 + c + 4];
        y = y > 0.f ? y : 0.f;
        ov1[c] = hv[c + 4] + y;
    }
    float4* o = reinterpret_cast<float4*>(h_out + (size_t)n * H_DIM + col0);
    __stcs(o, o0);
    __stcs(o + 1, o1);
}

// ---------------------------------------------------------------------------
extern "C" void kernel_launch(void* const* d_in, const int* in_sizes, int n_in,
                              void* d_out, int out_size)
{
    const float* h  = (const float*)d_in[0];
    const float* e  = (const float*)d_in[1];
    const int*   ei = (const int*)  d_in[2];
    const float* Wu = (const float*)d_in[3];
    const float* bu = (const float*)d_in[4];
    const float* Wv = (const float*)d_in[5];
    const float* bv = (const float*)d_in[6];
    const float* Wa = (const float*)d_in[7];
    const float* ba = (const float*)d_in[8];
    const float* Wb = (const float*)d_in[9];
    const float* bb = (const float*)d_in[10];
    const float* Wc = (const float*)d_in[11];
    const float* bc = (const float*)d_in[12];
    const float* gh = (const float*)d_in[13];
    const float* bh = (const float*)d_in[14];
    const float* ge = (const float*)d_in[15];
    const float* be = (const float*)d_in[16];

    const int V = in_sizes[0] / H_DIM;
    const int E = in_sizes[1] / H_DIM;

    float* h_out = (float*)d_out;
    float* e_out = (float*)d_out + (size_t)V * H_DIM;

    const int n4 = V * (H_DIM / 4);
    zero_agg_kernel<<<(n4 + 255) / 256, 256>>>(n4);

    dim3 g1((V + 63) / 64, 4);
    node_gemm_tc_kernel<<<g1, 256>>>(h, Wu, bu, Wv, bv, Wa, ba, Wb, bb, V);

    static int smem_set = 0;
    const int edge_smem = 64 * SE_STRIDE * sizeof(float);  // 66560B
    if (!smem_set) {
        cudaFuncSetAttribute(edge_fused_tc_kernel,
                             cudaFuncAttributeMaxDynamicSharedMemorySize, edge_smem);
        smem_set = 1;
    }
    edge_fused_tc_kernel<<<E / 64, 256, edge_smem>>>(e, ei, Wc, bc, ge, be, e_out, E, V);

    node_epilogue_kernel<<<(V + 7) / 8, 256>>>(h, gh, bh, h_out, V);
}

// round 4
// speedup vs baseline: 1.8509x; 1.3811x over previous
#include <cuda_runtime.h>
#include <math.h>

#define H_DIM 256
#define MAXV 10000
#define LN_EPS 1e-5f

// Scratch: [node][1024] = [Uh | Vh | Ah | Bh], plus aggregation buffer.
__device__ float g_nodebuf[(size_t)MAXV * 1024];
__device__ float g_agg[(size_t)MAXV * H_DIM];

// No "memory" clobber — ordering via data deps; clobber kills MLP batching.
__device__ __forceinline__ void red_add_v4(float* addr, float a, float b, float c, float d) {
    asm volatile("red.global.add.v4.f32 [%0], {%1,%2,%3,%4};"
                 :: "l"(addr), "f"(a), "f"(b), "f"(c), "f"(d));
}

__device__ __forceinline__ float to_tf32(float x) {
    float y;
    asm("cvt.rna.tf32.f32 %0, %1;" : "=f"(y) : "f"(x));
    return y;
}

__device__ __forceinline__ void mma_tf32(float& d0, float& d1, float& d2, float& d3,
                                         float a0, float a1, float a2, float a3,
                                         float b0, float b1) {
    asm volatile(
        "mma.sync.aligned.m16n8k8.row.col.f32.tf32.tf32.f32 "
        "{%0,%1,%2,%3}, {%4,%5,%6,%7}, {%8,%9}, {%0,%1,%2,%3};\n"
        : "+f"(d0), "+f"(d1), "+f"(d2), "+f"(d3)
        : "r"(__float_as_uint(a0)), "r"(__float_as_uint(a1)),
          "r"(__float_as_uint(a2)), "r"(__float_as_uint(a3)),
          "r"(__float_as_uint(b0)), "r"(__float_as_uint(b1)));
}

// Stride 36: fragment load bank = (36g + t) % 32 = (4g + t) % 32, a perfect
// permutation over (g in 0..7, t in 0..3) -> conflict-free. 36 words = 144B,
// 16B-aligned rows so float4 staging stores stay legal.
#define SA_STRIDE 36
#define SB_STRIDE 36
#define SE_STRIDE 264

// ---------------------------------------------------------------------------
// Kernel 0: zero the aggregation buffer (graph-replay safe)
// ---------------------------------------------------------------------------
__global__ void zero_agg_kernel(int n4) {
    int i = blockIdx.x * blockDim.x + threadIdx.x;
    if (i < n4) reinterpret_cast<float4*>(g_agg)[i] = make_float4(0.f, 0.f, 0.f, 0.f);
}

__device__ __forceinline__ float4 tf32_4(float4 v) {
    return make_float4(to_tf32(v.x), to_tf32(v.y), to_tf32(v.z), to_tf32(v.w));
}

// ---------------------------------------------------------------------------
// Kernel 1: node GEMM (tf32 mma)  C[64 x 256] per block = h @ W^T + bias
// ---------------------------------------------------------------------------
__global__ __launch_bounds__(256) void node_gemm_tc_kernel(
    const float* __restrict__ h,
    const float* __restrict__ Wu, const float* __restrict__ bu,
    const float* __restrict__ Wv, const float* __restrict__ bv,
    const float* __restrict__ Wa, const float* __restrict__ ba,
    const float* __restrict__ Wb, const float* __restrict__ bb,
    int V)
{
    __shared__ float sA[64 * SA_STRIDE];
    __shared__ float sB[256 * SB_STRIDE];

    const int by = blockIdx.y;
    const float* W; const float* bias;
    if      (by == 0) { W = Wu; bias = bu; }
    else if (by == 1) { W = Wv; bias = bv; }
    else if (by == 2) { W = Wa; bias = ba; }
    else              { W = Wb; bias = bb; }

    const int tid  = threadIdx.x;
    const int w    = tid >> 5;
    const int lane = tid & 31;
    const int g    = lane >> 2;
    const int t    = lane & 3;
    const int row0 = blockIdx.x * 64;

    const int lr  = tid >> 2;          // 0..63
    const int lk8 = (tid & 3) * 8;     // 0,8,16,24

    float acc[4][4][4];
    #pragma unroll
    for (int mt = 0; mt < 4; mt++)
        #pragma unroll
        for (int nt = 0; nt < 4; nt++)
            #pragma unroll
            for (int q = 0; q < 4; q++) acc[mt][nt][q] = 0.f;

    for (int kk = 0; kk < H_DIM; kk += 32) {
        {   // A tile: 64 rows x 32 k
            int gr = row0 + lr; if (gr >= V) gr = V - 1;
            const float* ar = h + (size_t)gr * H_DIM + kk + lk8;
            float4 v0 = __ldg(reinterpret_cast<const float4*>(ar));
            float4 v1 = __ldg(reinterpret_cast<const float4*>(ar + 4));
            float4* sa = reinterpret_cast<float4*>(sA + lr * SA_STRIDE + lk8);
            sa[0] = tf32_4(v0);
            sa[1] = tf32_4(v1);
        }
        {   // B tile
            const float* wr = W + (size_t)tid * H_DIM + kk;
            float4* sb = reinterpret_cast<float4*>(sB + tid * SB_STRIDE);
            #pragma unroll
            for (int q = 0; q < 8; q++) {
                float4 v = __ldg(reinterpret_cast<const float4*>(wr + q * 4));
                sb[q] = tf32_4(v);
            }
        }
        __syncthreads();
        #pragma unroll
        for (int ks = 0; ks < 4; ks++) {
            const int kb = ks * 8;
            float bf[4][2];
            #pragma unroll
            for (int nt = 0; nt < 4; nt++) {
                int n = w * 32 + nt * 8 + g;
                bf[nt][0] = sB[n * SB_STRIDE + kb + t];
                bf[nt][1] = sB[n * SB_STRIDE + kb + t + 4];
            }
            #pragma unroll
            for (int mt = 0; mt < 4; mt++) {
                int m = mt * 16;
                float a0 = sA[(m + g) * SA_STRIDE + kb + t];
                float a1 = sA[(m + g + 8) * SA_STRIDE + kb + t];
                float a2 = sA[(m + g) * SA_STRIDE + kb + t + 4];
                float a3 = sA[(m + g + 8) * SA_STRIDE + kb + t + 4];
                #pragma unroll
                for (int nt = 0; nt < 4; nt++)
                    mma_tf32(acc[mt][nt][0], acc[mt][nt][1], acc[mt][nt][2], acc[mt][nt][3],
                             a0, a1, a2, a3, bf[nt][0], bf[nt][1]);
            }
        }
        __syncthreads();
    }

    #pragma unroll
    for (int mt = 0; mt < 4; mt++) {
        #pragma unroll
        for (int nt = 0; nt < 4; nt++) {
            int c  = w * 32 + nt * 8 + 2 * t;
            int r0 = row0 + mt * 16 + g;
            int r1 = r0 + 8;
            if (r0 < V) {
                float* o = g_nodebuf + (size_t)r0 * 1024 + by * 256 + c;
                o[0] = acc[mt][nt][0] + bias[c];
                o[1] = acc[mt][nt][1] + bias[c + 1];
            }
            if (r1 < V) {
                float* o = g_nodebuf + (size_t)r1 * 1024 + by * 256 + c;
                o[0] = acc[mt][nt][2] + bias[c];
                o[1] = acc[mt][nt][3] + bias[c + 1];
            }
        }
    }
}

// ---------------------------------------------------------------------------
// Kernel 2: fused edge kernel (tf32 GEMM + gate/scatter/LN epilogue)
// ---------------------------------------------------------------------------
__global__ __launch_bounds__(256) void edge_fused_tc_kernel(
    const float* __restrict__ e,
    const int*   __restrict__ ei,      // [2][E]
    const float* __restrict__ Wc, const float* __restrict__ bc,
    const float* __restrict__ ge, const float* __restrict__ be,
    float* __restrict__ e_out,
    int E, int V)
{
    extern __shared__ float smem[];
    float* sA = smem;                   // [64][36]
    float* sB = smem + 64 * SA_STRIDE;  // [256][36]
    float* sE = smem;                   // [64][264] (reuses A/B region)

    __shared__ int   sSrc[64], sDst[64];
    __shared__ float sBc[256], sGe[256], sBe[256];

    const int tid = threadIdx.x;
    const int e0  = blockIdx.x * 64;

    if (tid < 64) {
        sSrc[tid] = ei[e0 + tid];
        sDst[tid] = ei[E + e0 + tid];
    }
    sBc[tid] = bc[tid]; sGe[tid] = ge[tid]; sBe[tid] = be[tid];

    const int w    = tid >> 5;
    const int lane = tid & 31;
    const int g    = lane >> 2;
    const int t    = lane & 3;

    const int lr  = tid >> 2;
    const int lk8 = (tid & 3) * 8;

    float acc[4][4][4];
    #pragma unroll
    for (int mt = 0; mt < 4; mt++)
        #pragma unroll
        for (int nt = 0; nt < 4; nt++)
            #pragma unroll
            for (int q = 0; q < 4; q++) acc[mt][nt][q] = 0.f;

    for (int kk = 0; kk < H_DIM; kk += 32) {
        {   // A tile: e rows, streaming (read once) -> evict-first
            const float* ar = e + (size_t)(e0 + lr) * H_DIM + kk + lk8;
            float4 v0 = __ldcs(reinterpret_cast<const float4*>(ar));
            float4 v1 = __ldcs(reinterpret_cast<const float4*>(ar + 4));
            float4* sa = reinterpret_cast<float4*>(sA + lr * SA_STRIDE + lk8);
            sa[0] = tf32_4(v0);
            sa[1] = tf32_4(v1);
        }
        {   // B tile: Wc rows (hot, normal policy)
            const float* wr = Wc + (size_t)tid * H_DIM + kk;
            float4* sb = reinterpret_cast<float4*>(sB + tid * SB_STRIDE);
            #pragma unroll
            for (int q = 0; q < 8; q++) {
                float4 v = __ldg(reinterpret_cast<const float4*>(wr + q * 4));
                sb[q] = tf32_4(v);
            }
        }
        __syncthreads();
        #pragma unroll
        for (int ks = 0; ks < 4; ks++) {
            const int kb = ks * 8;
            float bf[4][2];
            #pragma unroll
            for (int nt = 0; nt < 4; nt++) {
                int n = w * 32 + nt * 8 + g;
                bf[nt][0] = sB[n * SB_STRIDE + kb + t];
                bf[nt][1] = sB[n * SB_STRIDE + kb + t + 4];
            }
            #pragma unroll
            for (int mt = 0; mt < 4; mt++) {
                int m = mt * 16;
                float a0 = sA[(m + g) * SA_STRIDE + kb + t];
                float a1 = sA[(m + g + 8) * SA_STRIDE + kb + t];
                float a2 = sA[(m + g) * SA_STRIDE + kb + t + 4];
                float a3 = sA[(m + g + 8) * SA_STRIDE + kb + t + 4];
                #pragma unroll
                for (int nt = 0; nt < 4; nt++)
                    mma_tf32(acc[mt][nt][0], acc[mt][nt][1], acc[mt][nt][2], acc[mt][nt][3],
                             a0, a1, a2, a3, bf[nt][0], bf[nt][1]);
            }
        }
        __syncthreads();
    }

    // Stage Ce fragments into sE (reuses sA/sB region)
    #pragma unroll
    for (int mt = 0; mt < 4; mt++) {
        #pragma unroll
        for (int nt = 0; nt < 4; nt++) {
            int r = mt * 16 + g;
            int c = w * 32 + nt * 8 + 2 * t;
            sE[r * SE_STRIDE + c]       = acc[mt][nt][0];
            sE[r * SE_STRIDE + c + 1]   = acc[mt][nt][1];
            sE[(r + 8) * SE_STRIDE + c]     = acc[mt][nt][2];
            sE[(r + 8) * SE_STRIDE + c + 1] = acc[mt][nt][3];
        }
    }
    __syncthreads();

    // ---- fused epilogue: warp w owns rows w*8..w*8+7 fully ----
    const int col0 = lane * 8;

    #pragma unroll
    for (int i = 0; i < 8; i++) {
        const int r = w * 8 + i;
        const int er = e0 + r;
        const int s = sSrc[r];
        const int d = sDst[r];
        const float4* ah = reinterpret_cast<const float4*>(g_nodebuf + (size_t)d * 1024 + 512 + col0);
        const float4* bh = reinterpret_cast<const float4*>(g_nodebuf + (size_t)s * 1024 + 768 + col0);
        const float4* vh = reinterpret_cast<const float4*>(g_nodebuf + (size_t)d * 1024 + 256 + col0);

        float4 a0 = __ldg(ah), a1 = __ldg(ah + 1);
        float4 b0 = __ldg(bh), b1 = __ldg(bh + 1);
        float4 v0 = __ldg(vh), v1 = __ldg(vh + 1);
        float4 er0 = __ldcs(reinterpret_cast<const float4*>(e + (size_t)er * H_DIM + col0));
        float4 er1 = __ldcs(reinterpret_cast<const float4*>(e + (size_t)er * H_DIM + col0 + 4));

        float x[8], vhv[8], erv[8];
        {
            const float* se = sE + r * SE_STRIDE + col0;
            float4 u0 = *reinterpret_cast<const float4*>(se);
            float4 u1 = *reinterpret_cast<const float4*>(se + 4);
            x[0] = u0.x + a0.x + b0.x; x[1] = u0.y + a0.y + b0.y;
            x[2] = u0.z + a0.z + b0.z; x[3] = u0.w + a0.w + b0.w;
            x[4] = u1.x + a1.x + b1.x; x[5] = u1.y + a1.y + b1.y;
            x[6] = u1.z + a1.z + b1.z; x[7] = u1.w + a1.w + b1.w;
        }
        vhv[0] = v0.x; vhv[1] = v0.y; vhv[2] = v0.z; vhv[3] = v0.w;
        vhv[4] = v1.x; vhv[5] = v1.y; vhv[6] = v1.z; vhv[7] = v1.w;
        erv[0] = er0.x; erv[1] = er0.y; erv[2] = er0.z; erv[3] = er0.w;
        erv[4] = er1.x; erv[5] = er1.y; erv[6] = er1.z; erv[7] = er1.w;

        float sum = 0.f, sq = 0.f;
        #pragma unroll
        for (int c = 0; c < 8; c++) {
            float xv = x[c] + sBc[col0 + c];
            x[c] = xv;
            sum += xv;
            sq  += xv * xv;
        }

        float gv[8];
        #pragma unroll
        for (int c = 0; c < 8; c++) {
            float gt = 1.f / (1.f + __expf(-x[c]));
            gv[c] = gt * vhv[c];
        }
        float* ag = g_agg + (size_t)s * H_DIM + col0;
        red_add_v4(ag,     gv[0], gv[1], gv[2], gv[3]);
        red_add_v4(ag + 4, gv[4], gv[5], gv[6], gv[7]);

        #pragma unroll
        for (int off = 16; off > 0; off >>= 1) {
            sum += __shfl_xor_sync(0xFFFFFFFFu, sum, off);
            sq  += __shfl_xor_sync(0xFFFFFFFFu, sq,  off);
        }
        const float mu  = sum * (1.f / 256.f);
        const float var = sq * (1.f / 256.f) - mu * mu;
        const float rs  = rsqrtf(var + LN_EPS);

        float4 o0, o1;
        float* ov0 = &o0.x; float* ov1 = &o1.x;
        #pragma unroll
        for (int c = 0; c < 4; c++) {
            float y = (x[c] - mu) * rs * sGe[col0 + c] + sBe[col0 + c];
            y = y > 0.f ? y : 0.f;
            ov0[c] = erv[c] + y;
        }
        #pragma unroll
        for (int c = 0; c < 4; c++) {
            float y = (x[c + 4] - mu) * rs * sGe[col0 + c + 4] + sBe[col0 + c + 4];
            y = y > 0.f ? y : 0.f;
            ov1[c] = erv[c + 4] + y;
        }
        float4* orow = reinterpret_cast<float4*>(e_out + (size_t)er * H_DIM + col0);
        __stcs(orow, o0);
        __stcs(orow + 1, o1);
    }
}

// ---------------------------------------------------------------------------
// Kernel 3: node epilogue  h_out = h + relu(LN(Uh + agg))
// ---------------------------------------------------------------------------
__global__ __launch_bounds__(256) void node_epilogue_kernel(
    const float* __restrict__ h,
    const float* __restrict__ gh, const float* __restrict__ bhv,
    float* __restrict__ h_out, int V)
{
    const int warp = threadIdx.x >> 5;
    const int lane = threadIdx.x & 31;
    const int n = blockIdx.x * 8 + warp;
    if (n >= V) return;
    const int col0 = lane * 8;

    const float4* u  = reinterpret_cast<const float4*>(g_nodebuf + (size_t)n * 1024 + col0);
    const float4* ag = reinterpret_cast<const float4*>(g_agg     + (size_t)n * H_DIM + col0);
    const float4* hr = reinterpret_cast<const float4*>(h         + (size_t)n * H_DIM + col0);

    float4 u0 = __ldcs(u),  u1 = __ldcs(u + 1);
    float4 g0 = __ldcs(ag), g1 = __ldcs(ag + 1);
    float4 h0 = __ldcs(hr), h1 = __ldcs(hr + 1);

    float x[8], hv[8];
    x[0] = u0.x + g0.x; x[1] = u0.y + g0.y; x[2] = u0.z + g0.z; x[3] = u0.w + g0.w;
    x[4] = u1.x + g1.x; x[5] = u1.y + g1.y; x[6] = u1.z + g1.z; x[7] = u1.w + g1.w;
    hv[0] = h0.x; hv[1] = h0.y; hv[2] = h0.z; hv[3] = h0.w;
    hv[4] = h1.x; hv[5] = h1.y; hv[6] = h1.z; hv[7] = h1.w;

    float sum = 0.f, sq = 0.f;
    #pragma unroll
    for (int c = 0; c < 8; c++) { sum += x[c]; sq += x[c] * x[c]; }
    #pragma unroll
    for (int off = 16; off > 0; off >>= 1) {
        sum += __shfl_xor_sync(0xFFFFFFFFu, sum, off);
        sq  += __shfl_xor_sync(0xFFFFFFFFu, sq,  off);
    }
    const float mu  = sum * (1.f / 256.f);
    const float var = sq * (1.f / 256.f) - mu * mu;
    const float rs  = rsqrtf(var + LN_EPS);

    float4 o0, o1;
    float* ov0 = &o0.x; float* ov1 = &o1.x;
    #pragma unroll
    for (int c = 0; c < 4; c++) {
        float y = (x[c] - mu) * rs * gh[col0 + c] + bhv[col0 + c];
        y = y > 0.f ? y : 0.f;
        ov0[c] = hv[c] + y;
    }
    #pragma unroll
    for (int c = 0; c < 4; c++) {
        float y = (x[c + 4] - mu) * rs * gh[col0 + c + 4] + bhv[col0 + c + 4];
        y = y > 0.f ? y : 0.f;
        ov1[c] = hv[c + 4] + y;
    }
    float4* o = reinterpret_cast<float4*>(h_out + (size_t)n * H_DIM + col0);
    __stcs(o, o0);
    __stcs(o + 1, o1);
}

// ---------------------------------------------------------------------------
extern "C" void kernel_launch(void* const* d_in, const int* in_sizes, int n_in,
                              void* d_out, int out_size)
{
    const float* h  = (const float*)d_in[0];
    const float* e  = (const float*)d_in[1];
    const int*   ei = (const int*)  d_in[2];
    const float* Wu = (const float*)d_in[3];
    const float* bu = (const float*)d_in[4];
    const float* Wv = (const float*)d_in[5];
    const float* bv = (const float*)d_in[6];
    const float* Wa = (const float*)d_in[7];
    const float* ba = (const float*)d_in[8];
    const float* Wb = (const float*)d_in[9];
    const float* bb = (const float*)d_in[10];
    const float* Wc = (const float*)d_in[11];
    const float* bc = (const float*)d_in[12];
    const float* gh = (const float*)d_in[13];
    const float* bh = (const float*)d_in[14];
    const float* ge = (const float*)d_in[15];
    const float* be = (const float*)d_in[16];

    const int V = in_sizes[0] / H_DIM;
    const int E = in_sizes[1] / H_DIM;

    float* h_out = (float*)d_out;
    float* e_out = (float*)d_out + (size_t)V * H_DIM;

    const int n4 = V * (H_DIM / 4);
    zero_agg_kernel<<<(n4 + 255) / 256, 256>>>(n4);

    dim3 g1((V + 63) / 64, 4);
    node_gemm_tc_kernel<<<g1, 256>>>(h, Wu, bu, Wv, bv, Wa, ba, Wb, bb, V);

    static int smem_set = 0;
    const int edge_smem = 64 * SE_STRIDE * sizeof(float);  // 67584B, covers A+B (46KB) too
    if (!smem_set) {
        cudaFuncSetAttribute(edge_fused_tc_kernel,
                             cudaFuncAttributeMaxDynamicSharedMemorySize, edge_smem);
        smem_set = 1;
    }
    edge_fused_tc_kernel<<<E / 64, 256, edge_smem>>>(e, ei, Wc, bc, ge, be, e_out, E, V);

    node_epilogue_kernel<<<(V + 7) / 8, 256>>>(h, gh, bh, h_out, V);
}

// round 6
// speedup vs baseline: 1.8706x; 1.0107x over previous
#include <cuda_runtime.h>
#include <cstdint>
#include <cstddef>
#include <math.h>

#define H_DIM 256
#define MAXV 10000
#define LN_EPS 1e-5f

// Scratch: [node][1024] = [Uh | Vh | Ah | Bh], plus aggregation buffer.
__device__ float g_nodebuf[(size_t)MAXV * 1024];
__device__ float g_agg[(size_t)MAXV * H_DIM];
// tf32-rounded weights: [Wu | Wv | Wa | Wb | Wc], each 256x256.
__device__ float g_wtf[5 * 65536];

// No "memory" clobber — ordering via data deps; clobber kills MLP batching.
__device__ __forceinline__ void red_add_v4(float* addr, float a, float b, float c, float d) {
    asm volatile("red.global.add.v4.f32 [%0], {%1,%2,%3,%4};"
                 :: "l"(addr), "f"(a), "f"(b), "f"(c), "f"(d));
}

__device__ __forceinline__ float to_tf32(float x) {
    float y;
    asm("cvt.rna.tf32.f32 %0, %1;" : "=f"(y) : "f"(x));
    return y;
}

__device__ __forceinline__ float4 tf32_4(float4 v) {
    return make_float4(to_tf32(v.x), to_tf32(v.y), to_tf32(v.z), to_tf32(v.w));
}

__device__ __forceinline__ void mma_tf32(float& d0, float& d1, float& d2, float& d3,
                                         float a0, float a1, float a2, float a3,
                                         float b0, float b1) {
    asm volatile(
        "mma.sync.aligned.m16n8k8.row.col.f32.tf32.tf32.f32 "
        "{%0,%1,%2,%3}, {%4,%5,%6,%7}, {%8,%9}, {%0,%1,%2,%3};\n"
        : "+f"(d0), "+f"(d1), "+f"(d2), "+f"(d3)
        : "r"(__float_as_uint(a0)), "r"(__float_as_uint(a1)),
          "r"(__float_as_uint(a2)), "r"(__float_as_uint(a3)),
          "r"(__float_as_uint(b0)), "r"(__float_as_uint(b1)));
}

__device__ __forceinline__ void cpa16(uint32_t saddr, const void* g) {
    asm volatile("cp.async.cg.shared.global [%0], [%1], 16;" :: "r"(saddr), "l"(g));
}
__device__ __forceinline__ void cpa16_ef(uint32_t saddr, const void* g, uint64_t pol) {
    asm volatile("cp.async.cg.shared.global.L2::cache_hint [%0], [%1], 16, %2;"
                 :: "r"(saddr), "l"(g), "l"(pol));
}
__device__ __forceinline__ void cpa_commit() {
    asm volatile("cp.async.commit_group;");
}
template <int N>
__device__ __forceinline__ void cpa_wait() {
    asm volatile("cp.async.wait_group %0;" :: "n"(N));
}

// Stride 36: fragment load bank = (36g + t) % 32 = (4g + t) % 32, a perfect
// permutation over (g in 0..7, t in 0..3) -> conflict-free. 144B rows, 16B aligned.
#define SA_STRIDE 36
#define SB_STRIDE 36
#define SE_STRIDE 264

// smem layout (floats): A0[2304] A1[2304] B0[9216] B1[9216] = 23040 floats (92160B)
#define SA0_OFF 0
#define SA1_OFF 2304
#define SB0_OFF 4608
#define SB1_OFF 13824
#define GEMM_SMEM_BYTES 92160

// ---------------------------------------------------------------------------
// Kernel 0a: zero agg (graph-replay safe)
// ---------------------------------------------------------------------------
__global__ void zero_agg_kernel(int n4) {
    int i = blockIdx.x * blockDim.x + threadIdx.x;
    if (i < n4) reinterpret_cast<float4*>(g_agg)[i] = make_float4(0.f, 0.f, 0.f, 0.f);
}

// ---------------------------------------------------------------------------
// Kernel 0b: pre-round weights to tf32 (B operands)
// ---------------------------------------------------------------------------
__global__ void cvt_weights_kernel(
    const float* __restrict__ Wu, const float* __restrict__ Wv,
    const float* __restrict__ Wa, const float* __restrict__ Wb,
    const float* __restrict__ Wc)
{
    int i = blockIdx.x * blockDim.x + threadIdx.x;   // float4 index, 81920 total
    int m = i >> 14;                                  // 16384 float4 per matrix
    int r = i & 16383;
    const float* src = (m == 0) ? Wu : (m == 1) ? Wv : (m == 2) ? Wa : (m == 3) ? Wb : Wc;
    float4 v = __ldg(reinterpret_cast<const float4*>(src) + r);
    reinterpret_cast<float4*>(g_wtf)[i] = tf32_4(v);
}

// ---------------------------------------------------------------------------
// Kernel 1: node GEMM (tf32 mma, cp.async double-buffered)
// ---------------------------------------------------------------------------
__global__ __launch_bounds__(256) void node_gemm_tc_kernel(
    const float* __restrict__ h,
    const float* __restrict__ bu, const float* __restrict__ bv,
    const float* __restrict__ ba, const float* __restrict__ bb,
    int V)
{
    extern __shared__ float smem[];
    const uint32_t smem_u32 = (uint32_t)__cvta_generic_to_shared(smem);

    const int by = blockIdx.y;
    const float* W = g_wtf + (size_t)by * 65536;   // tf32-rounded
    const float* bias = (by == 0) ? bu : (by == 1) ? bv : (by == 2) ? ba : bb;

    const int tid  = threadIdx.x;
    const int w    = tid >> 5;
    const int lane = tid & 31;
    const int g    = lane >> 2;
    const int t    = lane & 3;
    const int row0 = blockIdx.x * 64;

    const int lr  = tid >> 2;          // 0..63
    const int lk8 = (tid & 3) * 8;     // 0,8,16,24

    int gr = row0 + lr; if (gr >= V) gr = V - 1;    // clamp (stores guarded)
    const float* arow = h + (size_t)gr * H_DIM + lk8;
    const float* brow = W + (size_t)tid * H_DIM;

    const uint32_t sa_a[2] = { smem_u32 + (SA0_OFF + lr * SA_STRIDE + lk8) * 4,
                               smem_u32 + (SA1_OFF + lr * SA_STRIDE + lk8) * 4 };
    const uint32_t sb_a[2] = { smem_u32 + (SB0_OFF + tid * SB_STRIDE) * 4,
                               smem_u32 + (SB1_OFF + tid * SB_STRIDE) * 4 };

    float acc[4][4][4];
    #pragma unroll
    for (int mt = 0; mt < 4; mt++)
        #pragma unroll
        for (int nt = 0; nt < 4; nt++)
            #pragma unroll
            for (int q = 0; q < 4; q++) acc[mt][nt][q] = 0.f;

    // prologue: stage chunk 0 into buf 0
    cpa16(sa_a[0],      arow);
    cpa16(sa_a[0] + 16, arow + 4);
    #pragma unroll
    for (int q = 0; q < 8; q++) cpa16(sb_a[0] + q * 16, brow + q * 4);
    cpa_commit();

    #pragma unroll
    for (int c = 0; c < 8; c++) {
        const int buf = c & 1;
        if (c < 7) {
            const int nbuf = buf ^ 1;
            const int kk = (c + 1) * 32;
            cpa16(sa_a[nbuf],      arow + kk);
            cpa16(sa_a[nbuf] + 16, arow + kk + 4);
            #pragma unroll
            for (int q = 0; q < 8; q++) cpa16(sb_a[nbuf] + q * 16, brow + kk + q * 4);
            cpa_commit();
            cpa_wait<1>();
        } else {
            cpa_wait<0>();
        }
        __syncthreads();

        const float* sA = smem + (buf ? SA1_OFF : SA0_OFF);
        const float* sB = smem + (buf ? SB1_OFF : SB0_OFF);
        #pragma unroll
        for (int ks = 0; ks < 4; ks++) {
            const int kb = ks * 8;
            float bf[4][2];
            #pragma unroll
            for (int nt = 0; nt < 4; nt++) {
                int n = w * 32 + nt * 8 + g;
                bf[nt][0] = sB[n * SB_STRIDE + kb + t];
                bf[nt][1] = sB[n * SB_STRIDE + kb + t + 4];
            }
            #pragma unroll
            for (int mt = 0; mt < 4; mt++) {
                int m = mt * 16;
                float a0 = sA[(m + g) * SA_STRIDE + kb + t];
                float a1 = sA[(m + g + 8) * SA_STRIDE + kb + t];
                float a2 = sA[(m + g) * SA_STRIDE + kb + t + 4];
                float a3 = sA[(m + g + 8) * SA_STRIDE + kb + t + 4];
                #pragma unroll
                for (int nt = 0; nt < 4; nt++)
                    mma_tf32(acc[mt][nt][0], acc[mt][nt][1], acc[mt][nt][2], acc[mt][nt][3],
                             a0, a1, a2, a3, bf[nt][0], bf[nt][1]);
            }
        }
        __syncthreads();
    }

    #pragma unroll
    for (int mt = 0; mt < 4; mt++) {
        #pragma unroll
        for (int nt = 0; nt < 4; nt++) {
            int cc = w * 32 + nt * 8 + 2 * t;
            int r0 = row0 + mt * 16 + g;
            int r1 = r0 + 8;
            if (r0 < V) {
                float* o = g_nodebuf + (size_t)r0 * 1024 + by * 256 + cc;
                o[0] = acc[mt][nt][0] + bias[cc];
                o[1] = acc[mt][nt][1] + bias[cc + 1];
            }
            if (r1 < V) {
                float* o = g_nodebuf + (size_t)r1 * 1024 + by * 256 + cc;
                o[0] = acc[mt][nt][2] + bias[cc];
                o[1] = acc[mt][nt][3] + bias[cc + 1];
            }
        }
    }
}

// ---------------------------------------------------------------------------
// Kernel 2: fused edge kernel (cp.async double-buffered tf32 GEMM + epilogue)
// ---------------------------------------------------------------------------
__global__ __launch_bounds__(256) void edge_fused_tc_kernel(
    const float* __restrict__ e,
    const int*   __restrict__ ei,      // [2][E]
    const float* __restrict__ bc,
    const float* __restrict__ ge, const float* __restrict__ be,
    float* __restrict__ e_out,
    int E, int V)
{
    extern __shared__ float smem[];
    const uint32_t smem_u32 = (uint32_t)__cvta_generic_to_shared(smem);
    float* sE = smem;                   // [64][264], reuses GEMM buffers post-loop

    __shared__ int   sSrc[64], sDst[64];
    __shared__ float sBc[256], sGe[256], sBe[256];

    const int tid = threadIdx.x;
    const int e0  = blockIdx.x * 64;

    if (tid < 64) {
        sSrc[tid] = ei[e0 + tid];
        sDst[tid] = ei[E + e0 + tid];
    }
    sBc[tid] = bc[tid]; sGe[tid] = ge[tid]; sBe[tid] = be[tid];

    const int w    = tid >> 5;
    const int lane = tid & 31;
    const int g    = lane >> 2;
    const int t    = lane & 3;

    const int lr  = tid >> 2;
    const int lk8 = (tid & 3) * 8;

    uint64_t pol;
    asm("createpolicy.fractional.L2::evict_first.b64 %0, 1.0;" : "=l"(pol));

    const float* Wcv = g_wtf + 4 * 65536;           // tf32-rounded Wc
    const float* arow = e + (size_t)(e0 + lr) * H_DIM + lk8;   // E % 64 == 0
    const float* brow = Wcv + (size_t)tid * H_DIM;

    const uint32_t sa_a[2] = { smem_u32 + (SA0_OFF + lr * SA_STRIDE + lk8) * 4,
                               smem_u32 + (SA1_OFF + lr * SA_STRIDE + lk8) * 4 };
    const uint32_t sb_a[2] = { smem_u32 + (SB0_OFF + tid * SB_STRIDE) * 4,
                               smem_u32 + (SB1_OFF + tid * SB_STRIDE) * 4 };

    float acc[4][4][4];
    #pragma unroll
    for (int mt = 0; mt < 4; mt++)
        #pragma unroll
        for (int nt = 0; nt < 4; nt++)
            #pragma unroll
            for (int q = 0; q < 4; q++) acc[mt][nt][q] = 0.f;

    // prologue
    cpa16_ef(sa_a[0],      arow,     pol);
    cpa16_ef(sa_a[0] + 16, arow + 4, pol);
    #pragma unroll
    for (int q = 0; q < 8; q++) cpa16(sb_a[0] + q * 16, brow + q * 4);
    cpa_commit();

    #pragma unroll
    for (int c = 0; c < 8; c++) {
        const int buf = c & 1;
        if (c < 7) {
            const int nbuf = buf ^ 1;
            const int kk = (c + 1) * 32;
            cpa16_ef(sa_a[nbuf],      arow + kk,     pol);
            cpa16_ef(sa_a[nbuf] + 16, arow + kk + 4, pol);
            #pragma unroll
            for (int q = 0; q < 8; q++) cpa16(sb_a[nbuf] + q * 16, brow + kk + q * 4);
            cpa_commit();
            cpa_wait<1>();
        } else {
            cpa_wait<0>();
        }
        __syncthreads();

        const float* sA = smem + (buf ? SA1_OFF : SA0_OFF);
        const float* sB = smem + (buf ? SB1_OFF : SB0_OFF);
        #pragma unroll
        for (int ks = 0; ks < 4; ks++) {
            const int kb = ks * 8;
            float bf[4][2];
            #pragma unroll
            for (int nt = 0; nt < 4; nt++) {
                int n = w * 32 + nt * 8 + g;
                bf[nt][0] = sB[n * SB_STRIDE + kb + t];
                bf[nt][1] = sB[n * SB_STRIDE + kb + t + 4];
            }
            #pragma unroll
            for (int mt = 0; mt < 4; mt++) {
                int m = mt * 16;
                float a0 = sA[(m + g) * SA_STRIDE + kb + t];
                float a1 = sA[(m + g + 8) * SA_STRIDE + kb + t];
                float a2 = sA[(m + g) * SA_STRIDE + kb + t + 4];
                float a3 = sA[(m + g + 8) * SA_STRIDE + kb + t + 4];
                #pragma unroll
                for (int nt = 0; nt < 4; nt++)
                    mma_tf32(acc[mt][nt][0], acc[mt][nt][1], acc[mt][nt][2], acc[mt][nt][3],
                             a0, a1, a2, a3, bf[nt][0], bf[nt][1]);
            }
        }
        __syncthreads();
    }

    // Stage Ce fragments into sE (reuses GEMM buffers; all smem reads done)
    #pragma unroll
    for (int mt = 0; mt < 4; mt++) {
        #pragma unroll
        for (int nt = 0; nt < 4; nt++) {
            int r = mt * 16 + g;
            int cc = w * 32 + nt * 8 + 2 * t;
            sE[r * SE_STRIDE + cc]       = acc[mt][nt][0];
            sE[r * SE_STRIDE + cc + 1]   = acc[mt][nt][1];
            sE[(r + 8) * SE_STRIDE + cc]     = acc[mt][nt][2];
            sE[(r + 8) * SE_STRIDE + cc + 1] = acc[mt][nt][3];
        }
    }
    __syncthreads();

    // ---- fused epilogue: warp w owns rows w*8..w*8+7 fully ----
    const int col0 = lane * 8;

    #pragma unroll
    for (int i = 0; i < 8; i++) {
        const int r = w * 8 + i;
        const int er = e0 + r;
        const int s = sSrc[r];
        const int d = sDst[r];
        const float4* ah = reinterpret_cast<const float4*>(g_nodebuf + (size_t)d * 1024 + 512 + col0);
        const float4* bh = reinterpret_cast<const float4*>(g_nodebuf + (size_t)s * 1024 + 768 + col0);
        const float4* vh = reinterpret_cast<const float4*>(g_nodebuf + (size_t)d * 1024 + 256 + col0);

        float4 a0 = __ldg(ah), a1 = __ldg(ah + 1);
        float4 b0 = __ldg(bh), b1 = __ldg(bh + 1);
        float4 v0 = __ldg(vh), v1 = __ldg(vh + 1);
        float4 er0 = __ldcs(reinterpret_cast<const float4*>(e + (size_t)er * H_DIM + col0));
        float4 er1 = __ldcs(reinterpret_cast<const float4*>(e + (size_t)er * H_DIM + col0 + 4));

        float x[8], vhv[8], erv[8];
        {
            const float* se = sE + r * SE_STRIDE + col0;
            float4 u0 = *reinterpret_cast<const float4*>(se);
            float4 u1 = *reinterpret_cast<const float4*>(se + 4);
            x[0] = u0.x + a0.x + b0.x; x[1] = u0.y + a0.y + b0.y;
            x[2] = u0.z + a0.z + b0.z; x[3] = u0.w + a0.w + b0.w;
            x[4] = u1.x + a1.x + b1.x; x[5] = u1.y + a1.y + b1.y;
            x[6] = u1.z + a1.z + b1.z; x[7] = u1.w + a1.w + b1.w;
        }
        vhv[0] = v0.x; vhv[1] = v0.y; vhv[2] = v0.z; vhv[3] = v0.w;
        vhv[4] = v1.x; vhv[5] = v1.y; vhv[6] = v1.z; vhv[7] = v1.w;
        erv[0] = er0.x; erv[1] = er0.y; erv[2] = er0.z; erv[3] = er0.w;
        erv[4] = er1.x; erv[5] = er1.y; erv[6] = er1.z; erv[7] = er1.w;

        float sum = 0.f, sq = 0.f;
        #pragma unroll
        for (int cc = 0; cc < 8; cc++) {
            float xv = x[cc] + sBc[col0 + cc];
            x[cc] = xv;
            sum += xv;
            sq  += xv * xv;
        }

        float gv[8];
        #pragma unroll
        for (int cc = 0; cc < 8; cc++) {
            float gt = 1.f / (1.f + __expf(-x[cc]));
            gv[cc] = gt * vhv[cc];
        }
        float* ag = g_agg + (size_t)s * H_DIM + col0;
        red_add_v4(ag,     gv[0], gv[1], gv[2], gv[3]);
        red_add_v4(ag + 4, gv[4], gv[5], gv[6], gv[7]);

        #pragma unroll
        for (int off = 16; off > 0; off >>= 1) {
            sum += __shfl_xor_sync(0xFFFFFFFFu, sum, off);
            sq  += __shfl_xor_sync(0xFFFFFFFFu, sq,  off);
        }
        const float mu  = sum * (1.f / 256.f);
        const float var = sq * (1.f / 256.f) - mu * mu;
        const float rs  = rsqrtf(var + LN_EPS);

        float4 o0, o1;
        float* ov0 = &o0.x; float* ov1 = &o1.x;
        #pragma unroll
        for (int cc = 0; cc < 4; cc++) {
            float y = (x[cc] - mu) * rs * sGe[col0 + cc] + sBe[col0 + cc];
            y = y > 0.f ? y : 0.f;
            ov0[cc] = erv[cc] + y;
        }
        #pragma unroll
        for (int cc = 0; cc < 4; cc++) {
            float y = (x[cc + 4] - mu) * rs * sGe[col0 + cc + 4] + sBe[col0 + cc + 4];
            y = y > 0.f ? y : 0.f;
            ov1[cc] = erv[cc + 4] + y;
        }
        float4* orow = reinterpret_cast<float4*>(e_out + (size_t)er * H_DIM + col0);
        __stcs(orow, o0);
        __stcs(orow + 1, o1);
    }
}

// ---------------------------------------------------------------------------
// Kernel 3: node epilogue  h_out = h + relu(LN(Uh + agg))
// ---------------------------------------------------------------------------
__global__ __launch_bounds__(256) void node_epilogue_kernel(
    const float* __restrict__ h,
    const float* __restrict__ gh, const float* __restrict__ bhv,
    float* __restrict__ h_out, int V)
{
    const int warp = threadIdx.x >> 5;
    const int lane = threadIdx.x & 31;
    const int n = blockIdx.x * 8 + warp;
    if (n >= V) return;
    const int col0 = lane * 8;

    const float4* u  = reinterpret_cast<const float4*>(g_nodebuf + (size_t)n * 1024 + col0);
    const float4* ag = reinterpret_cast<const float4*>(g_agg     + (size_t)n * H_DIM + col0);
    const float4* hr = reinterpret_cast<const float4*>(h         + (size_t)n * H_DIM + col0);

    float4 u0 = __ldcs(u),  u1 = __ldcs(u + 1);
    float4 g0 = __ldcs(ag), g1 = __ldcs(ag + 1);
    float4 h0 = __ldcs(hr), h1 = __ldcs(hr + 1);

    float x[8], hv[8];
    x[0] = u0.x + g0.x; x[1] = u0.y + g0.y; x[2] = u0.z + g0.z; x[3] = u0.w + g0.w;
    x[4] = u1.x + g1.x; x[5] = u1.y + g1.y; x[6] = u1.z + g1.z; x[7] = u1.w + g1.w;
    hv[0] = h0.x; hv[1] = h0.y; hv[2] = h0.z; hv[3] = h0.w;
    hv[4] = h1.x; hv[5] = h1.y; hv[6] = h1.z; hv[7] = h1.w;

    float sum = 0.f, sq = 0.f;
    #pragma unroll
    for (int c = 0; c < 8; c++) { sum += x[c]; sq += x[c] * x[c]; }
    #pragma unroll
    for (int off = 16; off > 0; off >>= 1) {
        sum += __shfl_xor_sync(0xFFFFFFFFu, sum, off);
        sq  += __shfl_xor_sync(0xFFFFFFFFu, sq,  off);
    }
    const float mu  = sum * (1.f / 256.f);
    const float var = sq * (1.f / 256.f) - mu * mu;
    const float rs  = rsqrtf(var + LN_EPS);

    float4 o0, o1;
    float* ov0 = &o0.x; float* ov1 = &o1.x;
    #pragma unroll
    for (int c = 0; c < 4; c++) {
        float y = (x[c] - mu) * rs * gh[col0 + c] + bhv[col0 + c];
        y = y > 0.f ? y : 0.f;
        ov0[c] = hv[c] + y;
    }
    #pragma unroll
    for (int c = 0; c < 4; c++) {
        float y = (x[c + 4] - mu) * rs * gh[col0 + c + 4] + bhv[col0 + c + 4];
        y = y > 0.f ? y : 0.f;
        ov1[c] = hv[c + 4] + y;
    }
    float4* o = reinterpret_cast<float4*>(h_out + (size_t)n * H_DIM + col0);
    __stcs(o, o0);
    __stcs(o + 1, o1);
}

// ---------------------------------------------------------------------------
extern "C" void kernel_launch(void* const* d_in, const int* in_sizes, int n_in,
                              void* d_out, int out_size)
{
    const float* h  = (const float*)d_in[0];
    const float* e  = (const float*)d_in[1];
    const int*   ei = (const int*)  d_in[2];
    const float* Wu = (const float*)d_in[3];
    const float* bu = (const float*)d_in[4];
    const float* Wv = (const float*)d_in[5];
    const float* bv = (const float*)d_in[6];
    const float* Wa = (const float*)d_in[7];
    const float* ba = (const float*)d_in[8];
    const float* Wb = (const float*)d_in[9];
    const float* bb = (const float*)d_in[10];
    const float* Wc = (const float*)d_in[11];
    const float* bc = (const float*)d_in[12];
    const float* gh = (const float*)d_in[13];
    const float* bh = (const float*)d_in[14];
    const float* ge = (const float*)d_in[15];
    const float* be = (const float*)d_in[16];

    const int V = in_sizes[0] / H_DIM;
    const int E = in_sizes[1] / H_DIM;

    float* h_out = (float*)d_out;
    float* e_out = (float*)d_out + (size_t)V * H_DIM;

    static int attr_set = 0;
    if (!attr_set) {
        cudaFuncSetAttribute(node_gemm_tc_kernel,
                             cudaFuncAttributeMaxDynamicSharedMemorySize, GEMM_SMEM_BYTES);
        cudaFuncSetAttribute(edge_fused_tc_kernel,
                             cudaFuncAttributeMaxDynamicSharedMemorySize, GEMM_SMEM_BYTES);
        attr_set = 1;
    }

    const int n4 = V * (H_DIM / 4);
    zero_agg_kernel<<<(n4 + 255) / 256, 256>>>(n4);
    cvt_weights_kernel<<<320, 256>>>(Wu, Wv, Wa, Wb, Wc);

    dim3 g1((V + 63) / 64, 4);
    node_gemm_tc_kernel<<<g1, 256, GEMM_SMEM_BYTES>>>(h, bu, bv, ba, bb, V);

    edge_fused_tc_kernel<<<E / 64, 256, GEMM_SMEM_BYTES>>>(e, ei, bc, ge, be, e_out, E, V);

    node_epilogue_kernel<<<(V + 7) / 8, 256>>>(h, gh, bh, h_out, V);
}

// round 7
// speedup vs baseline: 2.2164x; 1.1849x over previous
#include <cuda_runtime.h>
#include <cstdint>
#include <cstddef>
#include <math.h>

#define H_DIM 256
#define MAXV 10000
#define LN_EPS 1e-5f

// Scratch: [node][1024] = [Uh | Vh | Ah | Bh], plus aggregation buffer.
__device__ float g_nodebuf[(size_t)MAXV * 1024];
__device__ float g_agg[(size_t)MAXV * H_DIM];
// tf32-rounded weights: [Wu | Wv | Wa | Wb | Wc], each 256x256.
__device__ float g_wtf[5 * 65536];

// No "memory" clobber — ordering via data deps; clobber kills MLP batching.
__device__ __forceinline__ void red_add_v4(float* addr, float a, float b, float c, float d) {
    asm volatile("red.global.add.v4.f32 [%0], {%1,%2,%3,%4};"
                 :: "l"(addr), "f"(a), "f"(b), "f"(c), "f"(d));
}

__device__ __forceinline__ float to_tf32(float x) {
    float y;
    asm("cvt.rna.tf32.f32 %0, %1;" : "=f"(y) : "f"(x));
    return y;
}

__device__ __forceinline__ float4 tf32_4(float4 v) {
    return make_float4(to_tf32(v.x), to_tf32(v.y), to_tf32(v.z), to_tf32(v.w));
}

__device__ __forceinline__ void mma_tf32(float& d0, float& d1, float& d2, float& d3,
                                         float a0, float a1, float a2, float a3,
                                         float b0, float b1) {
    asm volatile(
        "mma.sync.aligned.m16n8k8.row.col.f32.tf32.tf32.f32 "
        "{%0,%1,%2,%3}, {%4,%5,%6,%7}, {%8,%9}, {%0,%1,%2,%3};\n"
        : "+f"(d0), "+f"(d1), "+f"(d2), "+f"(d3)
        : "r"(__float_as_uint(a0)), "r"(__float_as_uint(a1)),
          "r"(__float_as_uint(a2)), "r"(__float_as_uint(a3)),
          "r"(__float_as_uint(b0)), "r"(__float_as_uint(b1)));
}

__device__ __forceinline__ void cpa16(uint32_t saddr, const void* g) {
    asm volatile("cp.async.cg.shared.global [%0], [%1], 16;" :: "r"(saddr), "l"(g));
}
__device__ __forceinline__ void cpa16_ef(uint32_t saddr, const void* g, uint64_t pol) {
    asm volatile("cp.async.cg.shared.global.L2::cache_hint [%0], [%1], 16, %2;"
                 :: "r"(saddr), "l"(g), "l"(pol));
}
__device__ __forceinline__ void cpa_commit() {
    asm volatile("cp.async.commit_group;");
}
template <int N>
__device__ __forceinline__ void cpa_wait() {
    asm volatile("cp.async.wait_group %0;" :: "n"(N));
}

// Stride 36: fragment load bank = (36g + t) % 32 = (4g + t) % 32, a perfect
// permutation over (g in 0..7, t in 0..3) -> conflict-free. 144B rows, 16B aligned.
#define SA_STRIDE 36
#define SB_STRIDE 36
#define SE_STRIDE 264

// smem layout (floats): A0[2304] A1[2304] B0[9216] B1[9216] = 23040 floats (92160B)
#define SA0_OFF 0
#define SA1_OFF 2304
#define SB0_OFF 4608
#define SB1_OFF 13824
#define GEMM_SMEM_BYTES 92160

// ---------------------------------------------------------------------------
// Kernel 0a: zero agg (graph-replay safe)
// ---------------------------------------------------------------------------
__global__ void zero_agg_kernel(int n4) {
    int i = blockIdx.x * blockDim.x + threadIdx.x;
    if (i < n4) reinterpret_cast<float4*>(g_agg)[i] = make_float4(0.f, 0.f, 0.f, 0.f);
}

// ---------------------------------------------------------------------------
// Kernel 0b: pre-round weights to tf32 (B operands)
// ---------------------------------------------------------------------------
__global__ void cvt_weights_kernel(
    const float* __restrict__ Wu, const float* __restrict__ Wv,
    const float* __restrict__ Wa, const float* __restrict__ Wb,
    const float* __restrict__ Wc)
{
    int i = blockIdx.x * blockDim.x + threadIdx.x;   // float4 index, 81920 total
    int m = i >> 14;                                  // 16384 float4 per matrix
    int r = i & 16383;
    const float* src = (m == 0) ? Wu : (m == 1) ? Wv : (m == 2) ? Wa : (m == 3) ? Wb : Wc;
    float4 v = __ldg(reinterpret_cast<const float4*>(src) + r);
    reinterpret_cast<float4*>(g_wtf)[i] = tf32_4(v);
}

// ---------------------------------------------------------------------------
// Kernel 1: node GEMM (tf32 mma, cp.async double-buffered)
// __launch_bounds__(256, 2): cap regs at 128 so 2 CTAs fit the 64K register file.
// ---------------------------------------------------------------------------
__global__ __launch_bounds__(256, 2) void node_gemm_tc_kernel(
    const float* __restrict__ h,
    const float* __restrict__ bu, const float* __restrict__ bv,
    const float* __restrict__ ba, const float* __restrict__ bb,
    int V)
{
    extern __shared__ float smem[];
    const uint32_t smem_u32 = (uint32_t)__cvta_generic_to_shared(smem);

    const int by = blockIdx.y;
    const float* W = g_wtf + (size_t)by * 65536;   // tf32-rounded
    const float* bias = (by == 0) ? bu : (by == 1) ? bv : (by == 2) ? ba : bb;

    const int tid  = threadIdx.x;
    const int w    = tid >> 5;
    const int lane = tid & 31;
    const int g    = lane >> 2;
    const int t    = lane & 3;
    const int row0 = blockIdx.x * 64;

    const int lr  = tid >> 2;          // 0..63
    const int lk8 = (tid & 3) * 8;     // 0,8,16,24

    int gr = row0 + lr; if (gr >= V) gr = V - 1;    // clamp (stores guarded)
    const float* arow = h + (size_t)gr * H_DIM + lk8;
    const float* brow = W + (size_t)tid * H_DIM;

    const uint32_t sa_a[2] = { smem_u32 + (SA0_OFF + lr * SA_STRIDE + lk8) * 4,
                               smem_u32 + (SA1_OFF + lr * SA_STRIDE + lk8) * 4 };
    const uint32_t sb_a[2] = { smem_u32 + (SB0_OFF + tid * SB_STRIDE) * 4,
                               smem_u32 + (SB1_OFF + tid * SB_STRIDE) * 4 };

    float acc[4][4][4];
    #pragma unroll
    for (int mt = 0; mt < 4; mt++)
        #pragma unroll
        for (int nt = 0; nt < 4; nt++)
            #pragma unroll
            for (int q = 0; q < 4; q++) acc[mt][nt][q] = 0.f;

    // prologue: stage chunk 0 into buf 0
    cpa16(sa_a[0],      arow);
    cpa16(sa_a[0] + 16, arow + 4);
    #pragma unroll
    for (int q = 0; q < 8; q++) cpa16(sb_a[0] + q * 16, brow + q * 4);
    cpa_commit();

    #pragma unroll
    for (int c = 0; c < 8; c++) {
        const int buf = c & 1;
        if (c < 7) {
            const int nbuf = buf ^ 1;
            const int kk = (c + 1) * 32;
            cpa16(sa_a[nbuf],      arow + kk);
            cpa16(sa_a[nbuf] + 16, arow + kk + 4);
            #pragma unroll
            for (int q = 0; q < 8; q++) cpa16(sb_a[nbuf] + q * 16, brow + kk + q * 4);
            cpa_commit();
            cpa_wait<1>();
        } else {
            cpa_wait<0>();
        }
        __syncthreads();

        const float* sA = smem + (buf ? SA1_OFF : SA0_OFF);
        const float* sB = smem + (buf ? SB1_OFF : SB0_OFF);
        #pragma unroll
        for (int ks = 0; ks < 4; ks++) {
            const int kb = ks * 8;
            float bf[4][2];
            #pragma unroll
            for (int nt = 0; nt < 4; nt++) {
                int n = w * 32 + nt * 8 + g;
                bf[nt][0] = sB[n * SB_STRIDE + kb + t];
                bf[nt][1] = sB[n * SB_STRIDE + kb + t + 4];
            }
            #pragma unroll
            for (int mt = 0; mt < 4; mt++) {
                int m = mt * 16;
                float a0 = sA[(m + g) * SA_STRIDE + kb + t];
                float a1 = sA[(m + g + 8) * SA_STRIDE + kb + t];
                float a2 = sA[(m + g) * SA_STRIDE + kb + t + 4];
                float a3 = sA[(m + g + 8) * SA_STRIDE + kb + t + 4];
                #pragma unroll
                for (int nt = 0; nt < 4; nt++)
                    mma_tf32(acc[mt][nt][0], acc[mt][nt][1], acc[mt][nt][2], acc[mt][nt][3],
                             a0, a1, a2, a3, bf[nt][0], bf[nt][1]);
            }
        }
        __syncthreads();
    }

    #pragma unroll
    for (int mt = 0; mt < 4; mt++) {
        #pragma unroll
        for (int nt = 0; nt < 4; nt++) {
            int cc = w * 32 + nt * 8 + 2 * t;
            int r0 = row0 + mt * 16 + g;
            int r1 = r0 + 8;
            if (r0 < V) {
                float* o = g_nodebuf + (size_t)r0 * 1024 + by * 256 + cc;
                o[0] = acc[mt][nt][0] + bias[cc];
                o[1] = acc[mt][nt][1] + bias[cc + 1];
            }
            if (r1 < V) {
                float* o = g_nodebuf + (size_t)r1 * 1024 + by * 256 + cc;
                o[0] = acc[mt][nt][2] + bias[cc];
                o[1] = acc[mt][nt][3] + bias[cc + 1];
            }
        }
    }
}

// ---------------------------------------------------------------------------
// Kernel 2: fused edge kernel (cp.async double-buffered tf32 GEMM + epilogue)
// __launch_bounds__(256, 2): regs capped at 128 -> 2 CTAs/SM; GEMM of one CTA
// overlaps the latency-bound epilogue of the other.
// ---------------------------------------------------------------------------
__global__ __launch_bounds__(256, 2) void edge_fused_tc_kernel(
    const float* __restrict__ e,
    const int*   __restrict__ ei,      // [2][E]
    const float* __restrict__ bc,
    const float* __restrict__ ge, const float* __restrict__ be,
    float* __restrict__ e_out,
    int E, int V)
{
    extern __shared__ float smem[];
    const uint32_t smem_u32 = (uint32_t)__cvta_generic_to_shared(smem);
    float* sE = smem;                   // [64][264], reuses GEMM buffers post-loop

    __shared__ int   sSrc[64], sDst[64];
    __shared__ float sBc[256], sGe[256], sBe[256];

    const int tid = threadIdx.x;
    const int e0  = blockIdx.x * 64;

    if (tid < 64) {
        sSrc[tid] = ei[e0 + tid];
        sDst[tid] = ei[E + e0 + tid];
    }
    sBc[tid] = bc[tid]; sGe[tid] = ge[tid]; sBe[tid] = be[tid];

    const int w    = tid >> 5;
    const int lane = tid & 31;
    const int g    = lane >> 2;
    const int t    = lane & 3;

    const int lr  = tid >> 2;
    const int lk8 = (tid & 3) * 8;

    uint64_t pol;
    asm("createpolicy.fractional.L2::evict_first.b64 %0, 1.0;" : "=l"(pol));

    const float* Wcv = g_wtf + 4 * 65536;           // tf32-rounded Wc
    const float* arow = e + (size_t)(e0 + lr) * H_DIM + lk8;   // E % 64 == 0
    const float* brow = Wcv + (size_t)tid * H_DIM;

    const uint32_t sa_a[2] = { smem_u32 + (SA0_OFF + lr * SA_STRIDE + lk8) * 4,
                               smem_u32 + (SA1_OFF + lr * SA_STRIDE + lk8) * 4 };
    const uint32_t sb_a[2] = { smem_u32 + (SB0_OFF + tid * SB_STRIDE) * 4,
                               smem_u32 + (SB1_OFF + tid * SB_STRIDE) * 4 };

    float acc[4][4][4];
    #pragma unroll
    for (int mt = 0; mt < 4; mt++)
        #pragma unroll
        for (int nt = 0; nt < 4; nt++)
            #pragma unroll
            for (int q = 0; q < 4; q++) acc[mt][nt][q] = 0.f;

    // prologue
    cpa16_ef(sa_a[0],      arow,     pol);
    cpa16_ef(sa_a[0] + 16, arow + 4, pol);
    #pragma unroll
    for (int q = 0; q < 8; q++) cpa16(sb_a[0] + q * 16, brow + q * 4);
    cpa_commit();

    #pragma unroll
    for (int c = 0; c < 8; c++) {
        const int buf = c & 1;
        if (c < 7) {
            const int nbuf = buf ^ 1;
            const int kk = (c + 1) * 32;
            cpa16_ef(sa_a[nbuf],      arow + kk,     pol);
            cpa16_ef(sa_a[nbuf] + 16, arow + kk + 4, pol);
            #pragma unroll
            for (int q = 0; q < 8; q++) cpa16(sb_a[nbuf] + q * 16, brow + kk + q * 4);
            cpa_commit();
            cpa_wait<1>();
        } else {
            cpa_wait<0>();
        }
        __syncthreads();

        const float* sA = smem + (buf ? SA1_OFF : SA0_OFF);
        const float* sB = smem + (buf ? SB1_OFF : SB0_OFF);
        #pragma unroll
        for (int ks = 0; ks < 4; ks++) {
            const int kb = ks * 8;
            float bf[4][2];
            #pragma unroll
            for (int nt = 0; nt < 4; nt++) {
                int n = w * 32 + nt * 8 + g;
                bf[nt][0] = sB[n * SB_STRIDE + kb + t];
                bf[nt][1] = sB[n * SB_STRIDE + kb + t + 4];
            }
            #pragma unroll
            for (int mt = 0; mt < 4; mt++) {
                int m = mt * 16;
                float a0 = sA[(m + g) * SA_STRIDE + kb + t];
                float a1 = sA[(m + g + 8) * SA_STRIDE + kb + t];
                float a2 = sA[(m + g) * SA_STRIDE + kb + t + 4];
                float a3 = sA[(m + g + 8) * SA_STRIDE + kb + t + 4];
                #pragma unroll
                for (int nt = 0; nt < 4; nt++)
                    mma_tf32(acc[mt][nt][0], acc[mt][nt][1], acc[mt][nt][2], acc[mt][nt][3],
                             a0, a1, a2, a3, bf[nt][0], bf[nt][1]);
            }
        }
        __syncthreads();
    }

    // Stage Ce fragments into sE (reuses GEMM buffers; all smem reads done)
    #pragma unroll
    for (int mt = 0; mt < 4; mt++) {
        #pragma unroll
        for (int nt = 0; nt < 4; nt++) {
            int r = mt * 16 + g;
            int cc = w * 32 + nt * 8 + 2 * t;
            sE[r * SE_STRIDE + cc]       = acc[mt][nt][0];
            sE[r * SE_STRIDE + cc + 1]   = acc[mt][nt][1];
            sE[(r + 8) * SE_STRIDE + cc]     = acc[mt][nt][2];
            sE[(r + 8) * SE_STRIDE + cc + 1] = acc[mt][nt][3];
        }
    }
    __syncthreads();

    // ---- fused epilogue: warp w owns rows w*8..w*8+7 fully ----
    const int col0 = lane * 8;

    #pragma unroll
    for (int i = 0; i < 8; i++) {
        const int r = w * 8 + i;
        const int er = e0 + r;
        const int s = sSrc[r];
        const int d = sDst[r];
        const float4* ah = reinterpret_cast<const float4*>(g_nodebuf + (size_t)d * 1024 + 512 + col0);
        const float4* bh = reinterpret_cast<const float4*>(g_nodebuf + (size_t)s * 1024 + 768 + col0);
        const float4* vh = reinterpret_cast<const float4*>(g_nodebuf + (size_t)d * 1024 + 256 + col0);

        float4 a0 = __ldg(ah), a1 = __ldg(ah + 1);
        float4 b0 = __ldg(bh), b1 = __ldg(bh + 1);
        float4 v0 = __ldg(vh), v1 = __ldg(vh + 1);
        float4 er0 = __ldcs(reinterpret_cast<const float4*>(e + (size_t)er * H_DIM + col0));
        float4 er1 = __ldcs(reinterpret_cast<const float4*>(e + (size_t)er * H_DIM + col0 + 4));

        float x[8], vhv[8], erv[8];
        {
            const float* se = sE + r * SE_STRIDE + col0;
            float4 u0 = *reinterpret_cast<const float4*>(se);
            float4 u1 = *reinterpret_cast<const float4*>(se + 4);
            x[0] = u0.x + a0.x + b0.x; x[1] = u0.y + a0.y + b0.y;
            x[2] = u0.z + a0.z + b0.z; x[3] = u0.w + a0.w + b0.w;
            x[4] = u1.x + a1.x + b1.x; x[5] = u1.y + a1.y + b1.y;
            x[6] = u1.z + a1.z + b1.z; x[7] = u1.w + a1.w + b1.w;
        }
        vhv[0] = v0.x; vhv[1] = v0.y; vhv[2] = v0.z; vhv[3] = v0.w;
        vhv[4] = v1.x; vhv[5] = v1.y; vhv[6] = v1.z; vhv[7] = v1.w;
        erv[0] = er0.x; erv[1] = er0.y; erv[2] = er0.z; erv[3] = er0.w;
        erv[4] = er1.x; erv[5] = er1.y; erv[6] = er1.z; erv[7] = er1.w;

        float sum = 0.f, sq = 0.f;
        #pragma unroll
        for (int cc = 0; cc < 8; cc++) {
            float xv = x[cc] + sBc[col0 + cc];
            x[cc] = xv;
            sum += xv;
            sq  += xv * xv;
        }

        float gv[8];
        #pragma unroll
        for (int cc = 0; cc < 8; cc++) {
            float gt = 1.f / (1.f + __expf(-x[cc]));
            gv[cc] = gt * vhv[cc];
        }
        float* ag = g_agg + (size_t)s * H_DIM + col0;
        red_add_v4(ag,     gv[0], gv[1], gv[2], gv[3]);
        red_add_v4(ag + 4, gv[4], gv[5], gv[6], gv[7]);

        #pragma unroll
        for (int off = 16; off > 0; off >>= 1) {
            sum += __shfl_xor_sync(0xFFFFFFFFu, sum, off);
            sq  += __shfl_xor_sync(0xFFFFFFFFu, sq,  off);
        }
        const float mu  = sum * (1.f / 256.f);
        const float var = sq * (1.f / 256.f) - mu * mu;
        const float rs  = rsqrtf(var + LN_EPS);

        float4 o0, o1;
        float* ov0 = &o0.x; float* ov1 = &o1.x;
        #pragma unroll
        for (int cc = 0; cc < 4; cc++) {
            float y = (x[cc] - mu) * rs * sGe[col0 + cc] + sBe[col0 + cc];
            y = y > 0.f ? y : 0.f;
            ov0[cc] = erv[cc] + y;
        }
        #pragma unroll
        for (int cc = 0; cc < 4; cc++) {
            float y = (x[cc + 4] - mu) * rs * sGe[col0 + cc + 4] + sBe[col0 + cc + 4];
            y = y > 0.f ? y : 0.f;
            ov1[cc] = erv[cc + 4] + y;
        }
        float4* orow = reinterpret_cast<float4*>(e_out + (size_t)er * H_DIM + col0);
        __stcs(orow, o0);
        __stcs(orow + 1, o1);
    }
}

// ---------------------------------------------------------------------------
// Kernel 3: node epilogue  h_out = h + relu(LN(Uh + agg))
// ---------------------------------------------------------------------------
__global__ __launch_bounds__(256) void node_epilogue_kernel(
    const float* __restrict__ h,
    const float* __restrict__ gh, const float* __restrict__ bhv,
    float* __restrict__ h_out, int V)
{
    const int warp = threadIdx.x >> 5;
    const int lane = threadIdx.x & 31;
    const int n = blockIdx.x * 8 + warp;
    if (n >= V) return;
    const int col0 = lane * 8;

    const float4* u  = reinterpret_cast<const float4*>(g_nodebuf + (size_t)n * 1024 + col0);
    const float4* ag = reinterpret_cast<const float4*>(g_agg     + (size_t)n * H_DIM + col0);
    const float4* hr = reinterpret_cast<const float4*>(h         + (size_t)n * H_DIM + col0);

    float4 u0 = __ldcs(u),  u1 = __ldcs(u + 1);
    float4 g0 = __ldcs(ag), g1 = __ldcs(ag + 1);
    float4 h0 = __ldcs(hr), h1 = __ldcs(hr + 1);

    float x[8], hv[8];
    x[0] = u0.x + g0.x; x[1] = u0.y + g0.y; x[2] = u0.z + g0.z; x[3] = u0.w + g0.w;
    x[4] = u1.x + g1.x; x[5] = u1.y + g1.y; x[6] = u1.z + g1.z; x[7] = u1.w + g1.w;
    hv[0] = h0.x; hv[1] = h0.y; hv[2] = h0.z; hv[3] = h0.w;
    hv[4] = h1.x; hv[5] = h1.y; hv[6] = h1.z; hv[7] = h1.w;

    float sum = 0.f, sq = 0.f;
    #pragma unroll
    for (int c = 0; c < 8; c++) { sum += x[c]; sq += x[c] * x[c]; }
    #pragma unroll
    for (int off = 16; off > 0; off >>= 1) {
        sum += __shfl_xor_sync(0xFFFFFFFFu, sum, off);
        sq  += __shfl_xor_sync(0xFFFFFFFFu, sq,  off);
    }
    const float mu  = sum * (1.f / 256.f);
    const float var = sq * (1.f / 256.f) - mu * mu;
    const float rs  = rsqrtf(var + LN_EPS);

    float4 o0, o1;
    float* ov0 = &o0.x; float* ov1 = &o1.x;
    #pragma unroll
    for (int c = 0; c < 4; c++) {
        float y = (x[c] - mu) * rs * gh[col0 + c] + bhv[col0 + c];
        y = y > 0.f ? y : 0.f;
        ov0[c] = hv[c] + y;
    }
    #pragma unroll
    for (int c = 0; c < 4; c++) {
        float y = (x[c + 4] - mu) * rs * gh[col0 + c + 4] + bhv[col0 + c + 4];
        y = y > 0.f ? y : 0.f;
        ov1[c] = hv[c + 4] + y;
    }
    float4* o = reinterpret_cast<float4*>(h_out + (size_t)n * H_DIM + col0);
    __stcs(o, o0);
    __stcs(o + 1, o1);
}

// ---------------------------------------------------------------------------
extern "C" void kernel_launch(void* const* d_in, const int* in_sizes, int n_in,
                              void* d_out, int out_size)
{
    const float* h  = (const float*)d_in[0];
    const float* e  = (const float*)d_in[1];
    const int*   ei = (const int*)  d_in[2];
    const float* Wu = (const float*)d_in[3];
    const float* bu = (const float*)d_in[4];
    const float* Wv = (const float*)d_in[5];
    const float* bv = (const float*)d_in[6];
    const float* Wa = (const float*)d_in[7];
    const float* ba = (const float*)d_in[8];
    const float* Wb = (const float*)d_in[9];
    const float* bb = (const float*)d_in[10];
    const float* Wc = (const float*)d_in[11];
    const float* bc = (const float*)d_in[12];
    const float* gh = (const float*)d_in[13];
    const float* bh = (const float*)d_in[14];
    const float* ge = (const float*)d_in[15];
    const float* be = (const float*)d_in[16];

    const int V = in_sizes[0] / H_DIM;
    const int E = in_sizes[1] / H_DIM;

    float* h_out = (float*)d_out;
    float* e_out = (float*)d_out + (size_t)V * H_DIM;

    static int attr_set = 0;
    if (!attr_set) {
        cudaFuncSetAttribute(node_gemm_tc_kernel,
                             cudaFuncAttributeMaxDynamicSharedMemorySize, GEMM_SMEM_BYTES);
        cudaFuncSetAttribute(edge_fused_tc_kernel,
                             cudaFuncAttributeMaxDynamicSharedMemorySize, GEMM_SMEM_BYTES);
        attr_set = 1;
    }

    const int n4 = V * (H_DIM / 4);
    zero_agg_kernel<<<(n4 + 255) / 256, 256>>>(n4);
    cvt_weights_kernel<<<320, 256>>>(Wu, Wv, Wa, Wb, Wc);

    dim3 g1((V + 63) / 64, 4);
    node_gemm_tc_kernel<<<g1, 256, GEMM_SMEM_BYTES>>>(h, bu, bv, ba, bb, V);

    edge_fused_tc_kernel<<<E / 64, 256, GEMM_SMEM_BYTES>>>(e, ei, bc, ge, be, e_out, E, V);

    node_epilogue_kernel<<<(V + 7) / 8, 256>>>(h, gh, bh, h_out, V);
}